// round 1
// baseline (speedup 1.0000x reference)
#include <cuda_runtime.h>
#include <math.h>

// ---------------- problem constants ----------------
#define BB    2
#define SS    2048
#define DD    1024
#define HH    16
#define HD    64
#define MLPD  4096
#define MM    (BB*SS)          // 4096 rows
#define LOG_MAX_F 4.6051702f   // log(1/0.01)

// ---------------- scratch (device globals; no allocs allowed) ----------------
__device__ float g_xn [MM*DD];
__device__ float g_q  [MM*DD];
__device__ float g_k  [MM*DD];
__device__ float g_v  [MM*DD];
__device__ float g_ctx[MM*DD];
__device__ float g_x2 [MM*DD];
__device__ float g_h1 [MM*MLPD];

// ---------------- LayerNorm: one block per row (D=1024, 256 thr x float4) ----
__global__ void __launch_bounds__(256) ln_kernel(
    const float* __restrict__ x, const float* __restrict__ g,
    const float* __restrict__ beta, float* __restrict__ out)
{
    int row = blockIdx.x;
    int tid = threadIdx.x;
    const float4* xr = reinterpret_cast<const float4*>(x + (size_t)row * DD);
    float4 v = xr[tid];
    float s  = v.x + v.y + v.z + v.w;
    float ss = v.x*v.x + v.y*v.y + v.z*v.z + v.w*v.w;
    #pragma unroll
    for (int o = 16; o > 0; o >>= 1) {
        s  += __shfl_xor_sync(0xffffffffu, s,  o);
        ss += __shfl_xor_sync(0xffffffffu, ss, o);
    }
    __shared__ float rs[8], rss[8];
    __shared__ float s_mu, s_rstd;
    int w = tid >> 5;
    if ((tid & 31) == 0) { rs[w] = s; rss[w] = ss; }
    __syncthreads();
    if (tid == 0) {
        float S = 0.f, SSum = 0.f;
        #pragma unroll
        for (int i = 0; i < 8; i++) { S += rs[i]; SSum += rss[i]; }
        float mu  = S * (1.0f / DD);
        float var = SSum * (1.0f / DD) - mu * mu;
        s_mu = mu; s_rstd = rsqrtf(var + 1e-6f);
    }
    __syncthreads();
    float mu = s_mu, rstd = s_rstd;
    float4 gv = reinterpret_cast<const float4*>(g)[tid];
    float4 bv = reinterpret_cast<const float4*>(beta)[tid];
    float4 o4;
    o4.x = (v.x - mu) * rstd * gv.x + bv.x;
    o4.y = (v.y - mu) * rstd * gv.y + bv.y;
    o4.z = (v.z - mu) * rstd * gv.z + bv.z;
    o4.w = (v.w - mu) * rstd * gv.w + bv.w;
    reinterpret_cast<float4*>(out + (size_t)row * DD)[tid] = o4;
}

// ---------------- SGEMM: C = A[MxK] @ B[KxN] + bias (+resid | gelu) ---------
// EPI: 0 = bias only, 1 = bias + residual, 2 = bias then exact GELU
template<int EPI>
__global__ void __launch_bounds__(256) sgemm_kernel(
    const float* __restrict__ A, const float* __restrict__ B,
    const float* __restrict__ bias, const float* __restrict__ resid,
    float* __restrict__ C, int M, int N, int K)
{
    constexpr int BM = 128, BN = 128, BK = 16;
    __shared__ float As[BK][BM + 4];   // transposed A tile
    __shared__ float Bs[BK][BN];

    int tid = threadIdx.x;
    int ty = tid >> 4, tx = tid & 15;
    int rowBase = blockIdx.y * BM;
    int colBase = blockIdx.x * BN;

    int aRow = tid >> 2;            // 0..63
    int aCol = (tid & 3) * 4;       // 0,4,8,12
    int bRow = tid >> 5;            // 0..7
    int bCol = (tid & 31) * 4;      // 0..124

    float acc[8][8];
    #pragma unroll
    for (int i = 0; i < 8; i++)
        #pragma unroll
        for (int j = 0; j < 8; j++) acc[i][j] = 0.f;

    for (int kb = 0; kb < K; kb += BK) {
        #pragma unroll
        for (int t = 0; t < 2; t++) {
            int r = aRow + t * 64;
            float4 av = *reinterpret_cast<const float4*>(
                &A[(size_t)(rowBase + r) * K + kb + aCol]);
            As[aCol + 0][r] = av.x;
            As[aCol + 1][r] = av.y;
            As[aCol + 2][r] = av.z;
            As[aCol + 3][r] = av.w;
        }
        #pragma unroll
        for (int t = 0; t < 2; t++) {
            int kr = bRow + t * 8;
            *reinterpret_cast<float4*>(&Bs[kr][bCol]) =
                *reinterpret_cast<const float4*>(
                    &B[(size_t)(kb + kr) * N + colBase + bCol]);
        }
        __syncthreads();
        #pragma unroll
        for (int k = 0; k < BK; k++) {
            float a[8], b[8];
            *reinterpret_cast<float4*>(&a[0]) = *reinterpret_cast<float4*>(&As[k][ty * 8]);
            *reinterpret_cast<float4*>(&a[4]) = *reinterpret_cast<float4*>(&As[k][ty * 8 + 4]);
            *reinterpret_cast<float4*>(&b[0]) = *reinterpret_cast<float4*>(&Bs[k][tx * 8]);
            *reinterpret_cast<float4*>(&b[4]) = *reinterpret_cast<float4*>(&Bs[k][tx * 8 + 4]);
            #pragma unroll
            for (int i = 0; i < 8; i++)
                #pragma unroll
                for (int j = 0; j < 8; j++)
                    acc[i][j] += a[i] * b[j];
        }
        __syncthreads();
    }

    #pragma unroll
    for (int i = 0; i < 8; i++) {
        int row = rowBase + ty * 8 + i;
        #pragma unroll
        for (int j = 0; j < 8; j += 4) {
            int col = colBase + tx * 8 + j;
            float4 r4;
            float* rv = &r4.x;
            #pragma unroll
            for (int u = 0; u < 4; u++) {
                float c = acc[i][j + u] + bias[col + u];
                if (EPI == 1) c += resid[(size_t)row * N + col + u];
                if (EPI == 2) c = 0.5f * c * (1.0f + erff(c * 0.70710678118f));
                rv[u] = c;
            }
            *reinterpret_cast<float4*>(&C[(size_t)row * N + col]) = r4;
        }
    }
}

// ---------------- per-head L2 norm of q,k + temperature folded into q -------
__global__ void __launch_bounds__(256) qknorm_kernel(
    float* __restrict__ q, float* __restrict__ k,
    const float* __restrict__ logit_scale)
{
    int gid  = blockIdx.x * blockDim.x + threadIdx.x;
    int wid  = gid >> 5;
    int lane = gid & 31;
    int token = wid >> 4;     // / HH
    int h     = wid & 15;     // % HH
    float scale = __expf(fminf(logit_scale[h], LOG_MAX_F));

    float* qp = q + (size_t)token * DD + h * HD;
    float* kp = k + (size_t)token * DD + h * HD;
    float2 qv = reinterpret_cast<float2*>(qp)[lane];
    float2 kv = reinterpret_cast<float2*>(kp)[lane];
    float sq = qv.x * qv.x + qv.y * qv.y;
    float sk = kv.x * kv.x + kv.y * kv.y;
    #pragma unroll
    for (int o = 16; o > 0; o >>= 1) {
        sq += __shfl_xor_sync(0xffffffffu, sq, o);
        sk += __shfl_xor_sync(0xffffffffu, sk, o);
    }
    float iq = scale / fmaxf(sqrtf(sq), 1e-12f);
    float ik = 1.0f  / fmaxf(sqrtf(sk), 1e-12f);
    qv.x *= iq; qv.y *= iq;
    kv.x *= ik; kv.y *= ik;
    reinterpret_cast<float2*>(qp)[lane] = qv;
    reinterpret_cast<float2*>(kp)[lane] = kv;
}

// ---------------- flash attention: 64 queries/block, online softmax ---------
// q,k,v layout: [B,S,H,HD] == [M, D] row-major with head h at cols h*64..
__global__ void __launch_bounds__(256) flash_kernel(
    const float* __restrict__ q, const float* __restrict__ k,
    const float* __restrict__ v, float* __restrict__ o)
{
    __shared__ float Qs [64][64];   // [qrow][d]
    __shared__ float KPs[64][64];   // K as [d][key], reused as P [qrow][key]
    __shared__ float Vs [64][64];   // [key][d]

    int tid = threadIdx.x;
    int b  = blockIdx.z;
    int h  = blockIdx.y;
    int q0 = blockIdx.x * 64;
    const size_t base = (size_t)b * SS * DD + (size_t)h * HD;

    // Load Q tile (coalesced)
    #pragma unroll
    for (int t = 0; t < 4; t++) {
        int idx = t * 256 + tid;
        int r = idx >> 4; int c = (idx & 15) * 4;
        *reinterpret_cast<float4*>(&Qs[r][c]) =
            *reinterpret_cast<const float4*>(&q[base + (size_t)(q0 + r) * DD + c]);
    }

    int ty = tid >> 4, tx = tid & 15;
    float m[4], l[4], O[4][4];
    #pragma unroll
    for (int i = 0; i < 4; i++) {
        m[i] = -3.0e38f; l[i] = 0.f;
        #pragma unroll
        for (int j = 0; j < 4; j++) O[i][j] = 0.f;
    }

    for (int kv0 = 0; kv0 < SS; kv0 += 64) {
        __syncthreads();
        // K tile -> KPs transposed [d][key]; lane->key mapping keeps stores conflict-free
        #pragma unroll
        for (int t = 0; t < 4; t++) {
            int idx = t * 256 + tid;
            int key = idx & 63; int c4 = idx >> 6;   // c4 = 0..15
            float4 k4 = *reinterpret_cast<const float4*>(
                &k[base + (size_t)(kv0 + key) * DD + c4 * 4]);
            KPs[c4 * 4 + 0][key] = k4.x;
            KPs[c4 * 4 + 1][key] = k4.y;
            KPs[c4 * 4 + 2][key] = k4.z;
            KPs[c4 * 4 + 3][key] = k4.w;
        }
        // V tile natural layout (coalesced)
        #pragma unroll
        for (int t = 0; t < 4; t++) {
            int idx = t * 256 + tid;
            int key = idx >> 4; int c = (idx & 15) * 4;
            *reinterpret_cast<float4*>(&Vs[key][c]) =
                *reinterpret_cast<const float4*>(&v[base + (size_t)(kv0 + key) * DD + c]);
        }
        __syncthreads();

        // S = Q @ K^T  (each thread: rows ty*4.., keys tx*4..)
        float s[4][4];
        #pragma unroll
        for (int i = 0; i < 4; i++)
            #pragma unroll
            for (int j = 0; j < 4; j++) s[i][j] = 0.f;
        #pragma unroll
        for (int kk = 0; kk < 64; kk += 4) {
            float4 aq[4], bk[4];
            #pragma unroll
            for (int i = 0; i < 4; i++)
                aq[i] = *reinterpret_cast<float4*>(&Qs[ty * 4 + i][kk]);
            #pragma unroll
            for (int u = 0; u < 4; u++)
                bk[u] = *reinterpret_cast<float4*>(&KPs[kk + u][tx * 4]);
            #pragma unroll
            for (int i = 0; i < 4; i++) {
                const float* av = &aq[i].x;
                #pragma unroll
                for (int u = 0; u < 4; u++) {
                    s[i][0] += av[u] * bk[u].x;
                    s[i][1] += av[u] * bk[u].y;
                    s[i][2] += av[u] * bk[u].z;
                    s[i][3] += av[u] * bk[u].w;
                }
            }
        }

        // online softmax per row (row spread across 16 lanes sharing ty)
        float alpha[4];
        #pragma unroll
        for (int i = 0; i < 4; i++) {
            float tm = fmaxf(fmaxf(s[i][0], s[i][1]), fmaxf(s[i][2], s[i][3]));
            #pragma unroll
            for (int off = 8; off > 0; off >>= 1)
                tm = fmaxf(tm, __shfl_xor_sync(0xffffffffu, tm, off));
            float mnew = fmaxf(m[i], tm);
            alpha[i] = __expf(m[i] - mnew);
            float rsum = 0.f;
            #pragma unroll
            for (int j = 0; j < 4; j++) {
                s[i][j] = __expf(s[i][j] - mnew);
                rsum += s[i][j];
            }
            #pragma unroll
            for (int off = 8; off > 0; off >>= 1)
                rsum += __shfl_xor_sync(0xffffffffu, rsum, off);
            l[i] = l[i] * alpha[i] + rsum;
            m[i] = mnew;
            #pragma unroll
            for (int j = 0; j < 4; j++) O[i][j] *= alpha[i];
        }

        __syncthreads();   // all reads of KPs (K) done
        #pragma unroll
        for (int i = 0; i < 4; i++) {
            float4 p4; p4.x = s[i][0]; p4.y = s[i][1]; p4.z = s[i][2]; p4.w = s[i][3];
            *reinterpret_cast<float4*>(&KPs[ty * 4 + i][tx * 4]) = p4;
        }
        __syncthreads();   // P visible

        // O += P @ V
        #pragma unroll
        for (int kk = 0; kk < 64; kk += 4) {
            float4 ap[4], bv[4];
            #pragma unroll
            for (int i = 0; i < 4; i++)
                ap[i] = *reinterpret_cast<float4*>(&KPs[ty * 4 + i][kk]);
            #pragma unroll
            for (int u = 0; u < 4; u++)
                bv[u] = *reinterpret_cast<float4*>(&Vs[kk + u][tx * 4]);
            #pragma unroll
            for (int i = 0; i < 4; i++) {
                const float* av = &ap[i].x;
                #pragma unroll
                for (int u = 0; u < 4; u++) {
                    O[i][0] += av[u] * bv[u].x;
                    O[i][1] += av[u] * bv[u].y;
                    O[i][2] += av[u] * bv[u].z;
                    O[i][3] += av[u] * bv[u].w;
                }
            }
        }
    }

    // finalize + write
    #pragma unroll
    for (int i = 0; i < 4; i++) {
        float inv = 1.0f / l[i];
        int r = q0 + ty * 4 + i;
        float4 o4;
        o4.x = O[i][0] * inv; o4.y = O[i][1] * inv;
        o4.z = O[i][2] * inv; o4.w = O[i][3] * inv;
        *reinterpret_cast<float4*>(&o[base + (size_t)r * DD + tx * 4]) = o4;
    }
}

// ---------------- driver ----------------
extern "C" void kernel_launch(void* const* d_in, const int* in_sizes, int n_in,
                              void* d_out, int out_size)
{
    const float* x     = (const float*)d_in[0];
    const float* wq    = (const float*)d_in[1];
    const float* bq    = (const float*)d_in[2];
    const float* wk    = (const float*)d_in[3];
    const float* bk    = (const float*)d_in[4];
    const float* wv    = (const float*)d_in[5];
    const float* bv    = (const float*)d_in[6];
    const float* wo    = (const float*)d_in[7];
    const float* bo    = (const float*)d_in[8];
    const float* w1    = (const float*)d_in[9];
    const float* b1    = (const float*)d_in[10];
    const float* w2    = (const float*)d_in[11];
    const float* b2    = (const float*)d_in[12];
    const float* ln1_g = (const float*)d_in[13];
    const float* ln1_b = (const float*)d_in[14];
    const float* ln2_g = (const float*)d_in[15];
    const float* ln2_b = (const float*)d_in[16];
    const float* lscal = (const float*)d_in[17];
    float* out = (float*)d_out;

    float *xn, *qb, *kb_, *vb, *ctx, *x2, *h1;
    cudaGetSymbolAddress((void**)&xn,  g_xn);
    cudaGetSymbolAddress((void**)&qb,  g_q);
    cudaGetSymbolAddress((void**)&kb_, g_k);
    cudaGetSymbolAddress((void**)&vb,  g_v);
    cudaGetSymbolAddress((void**)&ctx, g_ctx);
    cudaGetSymbolAddress((void**)&x2,  g_x2);
    cudaGetSymbolAddress((void**)&h1,  g_h1);

    dim3 gQKV(DD / 128, MM / 128);        // (8, 32)
    dim3 gMLP1(MLPD / 128, MM / 128);     // (32, 32)

    ln_kernel<<<MM, 256>>>(x, ln1_g, ln1_b, xn);

    sgemm_kernel<0><<<gQKV, 256>>>(xn, wq, bq, nullptr, qb,  MM, DD, DD);
    sgemm_kernel<0><<<gQKV, 256>>>(xn, wk, bk, nullptr, kb_, MM, DD, DD);
    sgemm_kernel<0><<<gQKV, 256>>>(xn, wv, bv, nullptr, vb,  MM, DD, DD);

    qknorm_kernel<<<(MM * HH * 32) / 256, 256>>>(qb, kb_, lscal);

    flash_kernel<<<dim3(SS / 64, HH, BB), 256>>>(qb, kb_, vb, ctx);

    sgemm_kernel<1><<<gQKV, 256>>>(ctx, wo, bo, x, x2, MM, DD, DD);

    ln_kernel<<<MM, 256>>>(x2, ln2_g, ln2_b, xn);

    sgemm_kernel<2><<<gMLP1, 256>>>(xn, w1, b1, nullptr, h1, MM, MLPD, DD);

    sgemm_kernel<1><<<gQKV, 256>>>(h1, w2, b2, x2, out, MM, DD, MLPD);
}

// round 3
// speedup vs baseline: 1.6005x; 1.6005x over previous
#include <cuda_runtime.h>
#include <cuda_bf16.h>
#include <math.h>
#include <stdint.h>

// ---------------- problem constants ----------------
#define BB    2
#define SS    2048
#define DD    1024
#define HH    16
#define HD    64
#define MLPD  4096
#define MM    (BB*SS)          // 4096 rows
#define LOG_MAX_F 4.6051702f   // log(1/0.01)

// ---------------- scratch (device globals; no allocs allowed) ----------------
// split-bf16 activation buffers: [M, 2K] with hi in cols [0,K), lo in cols [K,2K)
__device__ __align__(16) __nv_bfloat16 g_xns [(size_t)MM * 2 * DD];
__device__ __align__(16) __nv_bfloat16 g_ctxs[(size_t)MM * 2 * DD];
__device__ __align__(16) __nv_bfloat16 g_h1s [(size_t)MM * 2 * MLPD];
// fp32 buffers
__device__ float g_q [MM*DD];
__device__ float g_k [MM*DD];
__device__ float g_v [MM*DD];
__device__ float g_x2[MM*DD];
// split+transposed weights: [N, 2K] bf16 (row n holds W[:,n] hi then lo)
__device__ __align__(16) __nv_bfloat16 g_wqs[(size_t)DD * 2 * DD];
__device__ __align__(16) __nv_bfloat16 g_wks[(size_t)DD * 2 * DD];
__device__ __align__(16) __nv_bfloat16 g_wvs[(size_t)DD * 2 * DD];
__device__ __align__(16) __nv_bfloat16 g_wos[(size_t)DD * 2 * DD];
__device__ __align__(16) __nv_bfloat16 g_w1s[(size_t)MLPD * 2 * DD];
__device__ __align__(16) __nv_bfloat16 g_w2s[(size_t)DD * 2 * MLPD];

__device__ __forceinline__ uint32_t smem_u32(const void* p) {
    return (uint32_t)__cvta_generic_to_shared(p);
}

__device__ __forceinline__ void split2(float v, __nv_bfloat16& hi, __nv_bfloat16& lo) {
    hi = __float2bfloat16(v);
    lo = __float2bfloat16(v - __bfloat162float(hi));
}

// ---------------- weight transpose + split: W[K,N] f32 -> out[N,2K] bf16 ----
__global__ void __launch_bounds__(256) wsplit_kernel(
    const float* __restrict__ W, __nv_bfloat16* __restrict__ out, int K, int N)
{
    __shared__ float t[32][33];
    int n0 = blockIdx.x * 32, k0 = blockIdx.y * 32;
    int tx = threadIdx.x, ty = threadIdx.y;
    #pragma unroll
    for (int i = ty; i < 32; i += 8)
        t[i][tx] = W[(size_t)(k0 + i) * N + n0 + tx];
    __syncthreads();
    #pragma unroll
    for (int i = ty; i < 32; i += 8) {
        int n = n0 + i, k = k0 + tx;
        float v = t[tx][i];
        __nv_bfloat16 hi, lo; split2(v, hi, lo);
        out[(size_t)n * 2 * K + k]     = hi;
        out[(size_t)n * 2 * K + K + k] = lo;
    }
}

// ---------------- LayerNorm -> split bf16 [row, 2D] -------------------------
__global__ void __launch_bounds__(256) ln_split_kernel(
    const float* __restrict__ x, const float* __restrict__ g,
    const float* __restrict__ beta, __nv_bfloat16* __restrict__ outs)
{
    int row = blockIdx.x;
    int tid = threadIdx.x;
    const float4* xr = reinterpret_cast<const float4*>(x + (size_t)row * DD);
    float4 v = xr[tid];
    float s  = v.x + v.y + v.z + v.w;
    float ss = v.x*v.x + v.y*v.y + v.z*v.z + v.w*v.w;
    #pragma unroll
    for (int o = 16; o > 0; o >>= 1) {
        s  += __shfl_xor_sync(0xffffffffu, s,  o);
        ss += __shfl_xor_sync(0xffffffffu, ss, o);
    }
    __shared__ float rs[8], rss[8];
    __shared__ float s_mu, s_rstd;
    int w = tid >> 5;
    if ((tid & 31) == 0) { rs[w] = s; rss[w] = ss; }
    __syncthreads();
    if (tid == 0) {
        float S = 0.f, SSum = 0.f;
        #pragma unroll
        for (int i = 0; i < 8; i++) { S += rs[i]; SSum += rss[i]; }
        float mu  = S * (1.0f / DD);
        float var = SSum * (1.0f / DD) - mu * mu;
        s_mu = mu; s_rstd = rsqrtf(var + 1e-6f);
    }
    __syncthreads();
    float mu = s_mu, rstd = s_rstd;
    float4 gv = reinterpret_cast<const float4*>(g)[tid];
    float4 bv = reinterpret_cast<const float4*>(beta)[tid];
    float o0 = (v.x - mu) * rstd * gv.x + bv.x;
    float o1 = (v.y - mu) * rstd * gv.y + bv.y;
    float o2 = (v.z - mu) * rstd * gv.z + bv.z;
    float o3 = (v.w - mu) * rstd * gv.w + bv.w;
    __nv_bfloat16 h0,h1,h2,h3,l0,l1,l2,l3;
    split2(o0,h0,l0); split2(o1,h1,l1); split2(o2,h2,l2); split2(o3,h3,l3);
    __nv_bfloat16* dst = outs + (size_t)row * 2 * DD + tid * 4;
    __nv_bfloat162 a; a.x = h0; a.y = h1;
    __nv_bfloat162 b; b.x = h2; b.y = h3;
    *reinterpret_cast<__nv_bfloat162*>(dst)     = a;
    *reinterpret_cast<__nv_bfloat162*>(dst + 2) = b;
    a.x = l0; a.y = l1; b.x = l2; b.y = l3;
    *reinterpret_cast<__nv_bfloat162*>(dst + DD)     = a;
    *reinterpret_cast<__nv_bfloat162*>(dst + DD + 2) = b;
}

// ---------------- HMMA GEMM: C[M,N] = A2(split) @ B2(split)^T + epilogue ----
// A2: [M, 2K] bf16 (hi|lo), B2: [N, 2K] bf16 (hi|lo).
// 3 passes: hi*hi + lo*hi + hi*lo, fp32 accumulators (mma.sync m16n8k16).
// EPI 0: bias -> Cf ; EPI 1: bias+resid -> Cf ; EPI 2: gelu(bias+acc) -> split Cs
template<int EPI>
__global__ void __launch_bounds__(256) hmma_gemm_kernel(
    const __nv_bfloat16* __restrict__ A2, const __nv_bfloat16* __restrict__ B2,
    const float* __restrict__ bias, const float* __restrict__ resid,
    float* __restrict__ Cf, __nv_bfloat16* __restrict__ Cs, int N, int K)
{
    __shared__ __align__(128) __nv_bfloat16 As[2][128][40];  // BK=32, pad to 40
    __shared__ __align__(128) __nv_bfloat16 Bs[2][128][40];

    const int tid  = threadIdx.x;
    const int lane = tid & 31;
    const int wid  = tid >> 5;
    const int wm = wid >> 2, wn = wid & 3;     // 2 x 4 warp grid, warp tile 64x32
    const int rowM0 = blockIdx.y * 128;
    const int colN0 = blockIdx.x * 128;

    const int KC = K >> 5;        // 32-wide chunks per pass
    const int NC = 3 * KC;
    const size_t strideA = 2 * (size_t)K;

    const int lrow = tid >> 2;          // 0..63
    const int lcol = (tid & 3) * 8;     // 0,8,16,24

    float acc[4][4][4];
    #pragma unroll
    for (int a = 0; a < 4; a++)
        #pragma unroll
        for (int b = 0; b < 4; b++)
            #pragma unroll
            for (int r = 0; r < 4; r++) acc[a][b][r] = 0.f;

    auto issue = [&](int c, int buf) {
        int p    = c / KC;
        int kc   = (c - p * KC) << 5;
        int aoff = (p == 1) ? K : 0;
        int boff = (p == 2) ? K : 0;
        #pragma unroll
        for (int it = 0; it < 2; it++) {
            int row = lrow + it * 64;
            const __nv_bfloat16* ag = A2 + (size_t)(rowM0 + row) * strideA + aoff + kc + lcol;
            const __nv_bfloat16* bg = B2 + (size_t)(colN0 + row) * strideA + boff + kc + lcol;
            uint32_t sa = smem_u32(&As[buf][row][lcol]);
            uint32_t sb = smem_u32(&Bs[buf][row][lcol]);
            asm volatile("cp.async.cg.shared.global [%0], [%1], 16;" :: "r"(sa), "l"(ag));
            asm volatile("cp.async.cg.shared.global [%0], [%1], 16;" :: "r"(sb), "l"(bg));
        }
    };

    issue(0, 0);
    asm volatile("cp.async.commit_group;" ::: "memory");

    for (int c = 0; c < NC; c++) {
        int buf = c & 1;
        if (c + 1 < NC) {
            issue(c + 1, buf ^ 1);
            asm volatile("cp.async.commit_group;" ::: "memory");
            asm volatile("cp.async.wait_group 1;" ::: "memory");
        } else {
            asm volatile("cp.async.wait_group 0;" ::: "memory");
        }
        __syncthreads();

        #pragma unroll
        for (int k16 = 0; k16 < 32; k16 += 16) {
            uint32_t af[4][4], bfr[4][2];
            #pragma unroll
            for (int im = 0; im < 4; im++) {
                uint32_t addr = smem_u32(
                    &As[buf][wm * 64 + im * 16 + (lane & 15)][k16 + (lane >> 4) * 8]);
                asm volatile("ldmatrix.sync.aligned.m8n8.x4.shared.b16 {%0,%1,%2,%3}, [%4];"
                    : "=r"(af[im][0]), "=r"(af[im][1]), "=r"(af[im][2]), "=r"(af[im][3])
                    : "r"(addr));
            }
            #pragma unroll
            for (int in_ = 0; in_ < 4; in_++) {
                uint32_t addr = smem_u32(
                    &Bs[buf][wn * 32 + in_ * 8 + (lane & 7)][k16 + ((lane >> 3) & 1) * 8]);
                asm volatile("ldmatrix.sync.aligned.m8n8.x2.shared.b16 {%0,%1}, [%2];"
                    : "=r"(bfr[in_][0]), "=r"(bfr[in_][1]) : "r"(addr));
            }
            #pragma unroll
            for (int im = 0; im < 4; im++)
                #pragma unroll
                for (int in_ = 0; in_ < 4; in_++)
                    asm volatile(
                        "mma.sync.aligned.m16n8k16.row.col.f32.bf16.bf16.f32 "
                        "{%0,%1,%2,%3}, {%4,%5,%6,%7}, {%8,%9}, {%0,%1,%2,%3};"
                        : "+f"(acc[im][in_][0]), "+f"(acc[im][in_][1]),
                          "+f"(acc[im][in_][2]), "+f"(acc[im][in_][3])
                        : "r"(af[im][0]), "r"(af[im][1]), "r"(af[im][2]), "r"(af[im][3]),
                          "r"(bfr[in_][0]), "r"(bfr[in_][1]));
        }
        __syncthreads();
    }

    // epilogue: d0,d1 -> (row g, cols 2t,2t+1); d2,d3 -> (row g+8)
    const int g = lane >> 2, t4 = lane & 3;
    #pragma unroll
    for (int im = 0; im < 4; im++) {
        #pragma unroll
        for (int half = 0; half < 2; half++) {
            int row = rowM0 + wm * 64 + im * 16 + g + half * 8;
            #pragma unroll
            for (int in_ = 0; in_ < 4; in_++) {
                int col = colN0 + wn * 32 + in_ * 8 + t4 * 2;
                float v0 = acc[im][in_][half * 2]     + bias[col];
                float v1 = acc[im][in_][half * 2 + 1] + bias[col + 1];
                if (EPI == 1) {
                    v0 += resid[(size_t)row * N + col];
                    v1 += resid[(size_t)row * N + col + 1];
                }
                if (EPI == 2) {
                    v0 = 0.5f * v0 * (1.0f + erff(v0 * 0.70710678118f));
                    v1 = 0.5f * v1 * (1.0f + erff(v1 * 0.70710678118f));
                    __nv_bfloat16 h0, h1, l0, l1;
                    split2(v0, h0, l0); split2(v1, h1, l1);
                    __nv_bfloat162 hp; hp.x = h0; hp.y = h1;
                    __nv_bfloat162 lp; lp.x = l0; lp.y = l1;
                    __nv_bfloat16* dst = Cs + (size_t)row * 2 * N + col;
                    *reinterpret_cast<__nv_bfloat162*>(dst)     = hp;
                    *reinterpret_cast<__nv_bfloat162*>(dst + N) = lp;
                } else {
                    float2 o; o.x = v0; o.y = v1;
                    *reinterpret_cast<float2*>(&Cf[(size_t)row * N + col]) = o;
                }
            }
        }
    }
}

// ---------------- per-head L2 norm of q,k + temperature folded into q -------
__global__ void __launch_bounds__(256) qknorm_kernel(
    float* __restrict__ q, float* __restrict__ k,
    const float* __restrict__ logit_scale)
{
    int gid  = blockIdx.x * blockDim.x + threadIdx.x;
    int wid  = gid >> 5;
    int lane = gid & 31;
    int token = wid >> 4;
    int h     = wid & 15;
    float scale = __expf(fminf(logit_scale[h], LOG_MAX_F));

    float* qp = q + (size_t)token * DD + h * HD;
    float* kp = k + (size_t)token * DD + h * HD;
    float2 qv = reinterpret_cast<float2*>(qp)[lane];
    float2 kv = reinterpret_cast<float2*>(kp)[lane];
    float sq = qv.x * qv.x + qv.y * qv.y;
    float sk = kv.x * kv.x + kv.y * kv.y;
    #pragma unroll
    for (int o = 16; o > 0; o >>= 1) {
        sq += __shfl_xor_sync(0xffffffffu, sq, o);
        sk += __shfl_xor_sync(0xffffffffu, sk, o);
    }
    float iq = scale / fmaxf(sqrtf(sq), 1e-12f);
    float ik = 1.0f  / fmaxf(sqrtf(sk), 1e-12f);
    qv.x *= iq; qv.y *= iq;
    kv.x *= ik; kv.y *= ik;
    reinterpret_cast<float2*>(qp)[lane] = qv;
    reinterpret_cast<float2*>(kp)[lane] = kv;
}

// ---------------- flash attention (fp32) -> split bf16 ctx ------------------
__global__ void __launch_bounds__(256) flash_kernel(
    const float* __restrict__ q, const float* __restrict__ k,
    const float* __restrict__ v, __nv_bfloat16* __restrict__ ctxs)
{
    __shared__ float Qs [64][64];
    __shared__ float KPs[64][64];
    __shared__ float Vs [64][64];

    int tid = threadIdx.x;
    int bz = blockIdx.z;
    int h  = blockIdx.y;
    int q0 = blockIdx.x * 64;
    const size_t base = (size_t)bz * SS * DD + (size_t)h * HD;

    #pragma unroll
    for (int t = 0; t < 4; t++) {
        int idx = t * 256 + tid;
        int r = idx >> 4; int c = (idx & 15) * 4;
        *reinterpret_cast<float4*>(&Qs[r][c]) =
            *reinterpret_cast<const float4*>(&q[base + (size_t)(q0 + r) * DD + c]);
    }

    int ty = tid >> 4, tx = tid & 15;
    float m[4], l[4], O[4][4];
    #pragma unroll
    for (int i = 0; i < 4; i++) {
        m[i] = -3.0e38f; l[i] = 0.f;
        #pragma unroll
        for (int j = 0; j < 4; j++) O[i][j] = 0.f;
    }

    for (int kv0 = 0; kv0 < SS; kv0 += 64) {
        __syncthreads();
        #pragma unroll
        for (int t = 0; t < 4; t++) {
            int idx = t * 256 + tid;
            int key = idx & 63; int c4 = idx >> 6;
            float4 k4 = *reinterpret_cast<const float4*>(
                &k[base + (size_t)(kv0 + key) * DD + c4 * 4]);
            KPs[c4 * 4 + 0][key] = k4.x;
            KPs[c4 * 4 + 1][key] = k4.y;
            KPs[c4 * 4 + 2][key] = k4.z;
            KPs[c4 * 4 + 3][key] = k4.w;
        }
        #pragma unroll
        for (int t = 0; t < 4; t++) {
            int idx = t * 256 + tid;
            int key = idx >> 4; int c = (idx & 15) * 4;
            *reinterpret_cast<float4*>(&Vs[key][c]) =
                *reinterpret_cast<const float4*>(&v[base + (size_t)(kv0 + key) * DD + c]);
        }
        __syncthreads();

        float s[4][4];
        #pragma unroll
        for (int i = 0; i < 4; i++)
            #pragma unroll
            for (int j = 0; j < 4; j++) s[i][j] = 0.f;
        #pragma unroll
        for (int kk = 0; kk < 64; kk += 4) {
            float4 aq[4], bk[4];
            #pragma unroll
            for (int i = 0; i < 4; i++)
                aq[i] = *reinterpret_cast<float4*>(&Qs[ty * 4 + i][kk]);
            #pragma unroll
            for (int u = 0; u < 4; u++)
                bk[u] = *reinterpret_cast<float4*>(&KPs[kk + u][tx * 4]);
            #pragma unroll
            for (int i = 0; i < 4; i++) {
                const float* av = &aq[i].x;
                #pragma unroll
                for (int u = 0; u < 4; u++) {
                    s[i][0] += av[u] * bk[u].x;
                    s[i][1] += av[u] * bk[u].y;
                    s[i][2] += av[u] * bk[u].z;
                    s[i][3] += av[u] * bk[u].w;
                }
            }
        }

        float alpha[4];
        #pragma unroll
        for (int i = 0; i < 4; i++) {
            float tm = fmaxf(fmaxf(s[i][0], s[i][1]), fmaxf(s[i][2], s[i][3]));
            #pragma unroll
            for (int off = 8; off > 0; off >>= 1)
                tm = fmaxf(tm, __shfl_xor_sync(0xffffffffu, tm, off));
            float mnew = fmaxf(m[i], tm);
            alpha[i] = __expf(m[i] - mnew);
            float rsum = 0.f;
            #pragma unroll
            for (int j = 0; j < 4; j++) {
                s[i][j] = __expf(s[i][j] - mnew);
                rsum += s[i][j];
            }
            #pragma unroll
            for (int off = 8; off > 0; off >>= 1)
                rsum += __shfl_xor_sync(0xffffffffu, rsum, off);
            l[i] = l[i] * alpha[i] + rsum;
            m[i] = mnew;
            #pragma unroll
            for (int j = 0; j < 4; j++) O[i][j] *= alpha[i];
        }

        __syncthreads();
        #pragma unroll
        for (int i = 0; i < 4; i++) {
            float4 p4; p4.x = s[i][0]; p4.y = s[i][1]; p4.z = s[i][2]; p4.w = s[i][3];
            *reinterpret_cast<float4*>(&KPs[ty * 4 + i][tx * 4]) = p4;
        }
        __syncthreads();

        #pragma unroll
        for (int kk = 0; kk < 64; kk += 4) {
            float4 ap[4], bv[4];
            #pragma unroll
            for (int i = 0; i < 4; i++)
                ap[i] = *reinterpret_cast<float4*>(&KPs[ty * 4 + i][kk]);
            #pragma unroll
            for (int u = 0; u < 4; u++)
                bv[u] = *reinterpret_cast<float4*>(&Vs[kk + u][tx * 4]);
            #pragma unroll
            for (int i = 0; i < 4; i++) {
                const float* av = &ap[i].x;
                #pragma unroll
                for (int u = 0; u < 4; u++) {
                    O[i][0] += av[u] * bv[u].x;
                    O[i][1] += av[u] * bv[u].y;
                    O[i][2] += av[u] * bv[u].z;
                    O[i][3] += av[u] * bv[u].w;
                }
            }
        }
    }

    #pragma unroll
    for (int i = 0; i < 4; i++) {
        float inv = 1.0f / l[i];
        int r = q0 + ty * 4 + i;
        int rowg = bz * SS + r;
        float v0 = O[i][0] * inv, v1 = O[i][1] * inv;
        float v2 = O[i][2] * inv, v3 = O[i][3] * inv;
        __nv_bfloat16 h0,h1,h2,h3,l0,l1,l2,l3;
        split2(v0,h0,l0); split2(v1,h1,l1); split2(v2,h2,l2); split2(v3,h3,l3);
        __nv_bfloat16* dst = ctxs + (size_t)rowg * 2 * DD + h * HD + tx * 4;
        __nv_bfloat162 a; a.x = h0; a.y = h1;
        __nv_bfloat162 b; b.x = h2; b.y = h3;
        *reinterpret_cast<__nv_bfloat162*>(dst)     = a;
        *reinterpret_cast<__nv_bfloat162*>(dst + 2) = b;
        a.x = l0; a.y = l1; b.x = l2; b.y = l3;
        *reinterpret_cast<__nv_bfloat162*>(dst + DD)     = a;
        *reinterpret_cast<__nv_bfloat162*>(dst + DD + 2) = b;
    }
}

// ---------------- driver ----------------
extern "C" void kernel_launch(void* const* d_in, const int* in_sizes, int n_in,
                              void* d_out, int out_size)
{
    const float* x     = (const float*)d_in[0];
    const float* wq    = (const float*)d_in[1];
    const float* bq    = (const float*)d_in[2];
    const float* wk    = (const float*)d_in[3];
    const float* bk    = (const float*)d_in[4];
    const float* wv    = (const float*)d_in[5];
    const float* bv    = (const float*)d_in[6];
    const float* wo    = (const float*)d_in[7];
    const float* bo    = (const float*)d_in[8];
    const float* w1    = (const float*)d_in[9];
    const float* b1    = (const float*)d_in[10];
    const float* w2    = (const float*)d_in[11];
    const float* b2    = (const float*)d_in[12];
    const float* ln1_g = (const float*)d_in[13];
    const float* ln1_b = (const float*)d_in[14];
    const float* ln2_g = (const float*)d_in[15];
    const float* ln2_b = (const float*)d_in[16];
    const float* lscal = (const float*)d_in[17];
    float* out = (float*)d_out;

    __nv_bfloat16 *xns, *ctxs, *h1s, *wqs, *wks, *wvs, *wos, *w1s, *w2s;
    float *qf, *kf, *vf, *x2f;
    cudaGetSymbolAddress((void**)&xns,  g_xns);
    cudaGetSymbolAddress((void**)&ctxs, g_ctxs);
    cudaGetSymbolAddress((void**)&h1s,  g_h1s);
    cudaGetSymbolAddress((void**)&wqs,  g_wqs);
    cudaGetSymbolAddress((void**)&wks,  g_wks);
    cudaGetSymbolAddress((void**)&wvs,  g_wvs);
    cudaGetSymbolAddress((void**)&wos,  g_wos);
    cudaGetSymbolAddress((void**)&w1s,  g_w1s);
    cudaGetSymbolAddress((void**)&w2s,  g_w2s);
    cudaGetSymbolAddress((void**)&qf,   g_q);
    cudaGetSymbolAddress((void**)&kf,   g_k);
    cudaGetSymbolAddress((void**)&vf,   g_v);
    cudaGetSymbolAddress((void**)&x2f,  g_x2);

    dim3 wb(32, 8);
    wsplit_kernel<<<dim3(DD/32,  DD/32),  wb>>>(wq, wqs, DD,   DD);
    wsplit_kernel<<<dim3(DD/32,  DD/32),  wb>>>(wk, wks, DD,   DD);
    wsplit_kernel<<<dim3(DD/32,  DD/32),  wb>>>(wv, wvs, DD,   DD);
    wsplit_kernel<<<dim3(DD/32,  DD/32),  wb>>>(wo, wos, DD,   DD);
    wsplit_kernel<<<dim3(MLPD/32, DD/32), wb>>>(w1, w1s, DD,   MLPD);
    wsplit_kernel<<<dim3(DD/32, MLPD/32), wb>>>(w2, w2s, MLPD, DD);

    ln_split_kernel<<<MM, 256>>>(x, ln1_g, ln1_b, xns);

    dim3 gQKV(DD / 128, MM / 128);     // (8, 32)
    dim3 gMLP1(MLPD / 128, MM / 128);  // (32, 32)

    hmma_gemm_kernel<0><<<gQKV, 256>>>(xns, wqs, bq, nullptr, qf, nullptr, DD, DD);
    hmma_gemm_kernel<0><<<gQKV, 256>>>(xns, wks, bk, nullptr, kf, nullptr, DD, DD);
    hmma_gemm_kernel<0><<<gQKV, 256>>>(xns, wvs, bv, nullptr, vf, nullptr, DD, DD);

    qknorm_kernel<<<(MM * HH * 32) / 256, 256>>>(qf, kf, lscal);

    flash_kernel<<<dim3(SS / 64, HH, BB), 256>>>(qf, kf, vf, ctxs);

    hmma_gemm_kernel<1><<<gQKV, 256>>>(ctxs, wos, bo, x, x2f, nullptr, DD, DD);

    ln_split_kernel<<<MM, 256>>>(x2f, ln2_g, ln2_b, xns);

    hmma_gemm_kernel<2><<<gMLP1, 256>>>(xns, w1s, b1, nullptr, nullptr, h1s, MLPD, DD);

    hmma_gemm_kernel<1><<<gQKV, 256>>>(h1s, w2s, b2, x2f, out, nullptr, DD, MLPD);
}

// round 4
// speedup vs baseline: 2.3019x; 1.4382x over previous
#include <cuda_runtime.h>
#include <cuda_bf16.h>
#include <math.h>
#include <stdint.h>

// ---------------- problem constants ----------------
#define BB    2
#define SS    2048
#define DD    1024
#define HH    16
#define HD    64
#define MLPD  4096
#define MM    (BB*SS)          // 4096 rows
#define LOG_MAX_F 4.6051702f   // log(1/0.01)

// ---------------- scratch (device globals; no allocs allowed) ----------------
__device__ __align__(16) __nv_bfloat16 g_xns [(size_t)MM * 2 * DD];
__device__ __align__(16) __nv_bfloat16 g_ctxs[(size_t)MM * 2 * DD];
__device__ __align__(16) __nv_bfloat16 g_h1s [(size_t)MM * 2 * MLPD];
__device__ float g_q [MM*DD];
__device__ float g_k [MM*DD];
__device__ float g_v [MM*DD];
__device__ float g_x2[MM*DD];
// per-head split q/k/v for flash: [b,h,s, (hi64|lo64)]
__device__ __align__(16) __nv_bfloat16 g_qsb[(size_t)BB*HH*SS*128];
__device__ __align__(16) __nv_bfloat16 g_ksb[(size_t)BB*HH*SS*128];
__device__ __align__(16) __nv_bfloat16 g_vsb[(size_t)BB*HH*SS*128];
// split+transposed weights: [N, 2K] bf16
__device__ __align__(16) __nv_bfloat16 g_wqs[(size_t)DD * 2 * DD];
__device__ __align__(16) __nv_bfloat16 g_wks[(size_t)DD * 2 * DD];
__device__ __align__(16) __nv_bfloat16 g_wvs[(size_t)DD * 2 * DD];
__device__ __align__(16) __nv_bfloat16 g_wos[(size_t)DD * 2 * DD];
__device__ __align__(16) __nv_bfloat16 g_w1s[(size_t)MLPD * 2 * DD];
__device__ __align__(16) __nv_bfloat16 g_w2s[(size_t)DD * 2 * MLPD];

__device__ __forceinline__ uint32_t smem_u32(const void* p) {
    return (uint32_t)__cvta_generic_to_shared(p);
}
__device__ __forceinline__ void split2(float v, __nv_bfloat16& hi, __nv_bfloat16& lo) {
    hi = __float2bfloat16(v);
    lo = __float2bfloat16(v - __bfloat162float(hi));
}
__device__ __forceinline__ void cp16(void* dst, const void* src) {
    asm volatile("cp.async.cg.shared.global [%0], [%1], 16;" :: "r"(smem_u32(dst)), "l"(src));
}
#define CP_COMMIT() asm volatile("cp.async.commit_group;" ::: "memory")
#define CP_WAIT(n)  asm volatile("cp.async.wait_group %0;" :: "n"(n) : "memory")

__device__ __forceinline__ void ldmA4(uint32_t* r, const void* p) {
    asm volatile("ldmatrix.sync.aligned.m8n8.x4.shared.b16 {%0,%1,%2,%3}, [%4];"
        : "=r"(r[0]), "=r"(r[1]), "=r"(r[2]), "=r"(r[3]) : "r"(smem_u32(p)));
}
__device__ __forceinline__ void ldmT4(uint32_t* r, const void* p) {
    asm volatile("ldmatrix.sync.aligned.m8n8.x4.trans.shared.b16 {%0,%1,%2,%3}, [%4];"
        : "=r"(r[0]), "=r"(r[1]), "=r"(r[2]), "=r"(r[3]) : "r"(smem_u32(p)));
}
__device__ __forceinline__ void mma16816(float* c, uint32_t a0, uint32_t a1, uint32_t a2,
                                         uint32_t a3, uint32_t b0, uint32_t b1) {
    asm volatile("mma.sync.aligned.m16n8k16.row.col.f32.bf16.bf16.f32 "
        "{%0,%1,%2,%3}, {%4,%5,%6,%7}, {%8,%9}, {%0,%1,%2,%3};"
        : "+f"(c[0]), "+f"(c[1]), "+f"(c[2]), "+f"(c[3])
        : "r"(a0), "r"(a1), "r"(a2), "r"(a3), "r"(b0), "r"(b1));
}
__device__ __forceinline__ void packsplit2(float x, float y, uint32_t& hi, uint32_t& lo) {
    __nv_bfloat16 hx, lx, hy, ly;
    split2(x, hx, lx); split2(y, hy, ly);
    __nv_bfloat162 hp; hp.x = hx; hp.y = hy;
    __nv_bfloat162 lp; lp.x = lx; lp.y = ly;
    hi = *reinterpret_cast<uint32_t*>(&hp);
    lo = *reinterpret_cast<uint32_t*>(&lp);
}

// ---------------- weight transpose + split: W[K,N] f32 -> out[N,2K] bf16 ----
__global__ void __launch_bounds__(256) wsplit_kernel(
    const float* __restrict__ W, __nv_bfloat16* __restrict__ out, int K, int N)
{
    __shared__ float t[32][33];
    int n0 = blockIdx.x * 32, k0 = blockIdx.y * 32;
    int tx = threadIdx.x, ty = threadIdx.y;
    #pragma unroll
    for (int i = ty; i < 32; i += 8)
        t[i][tx] = W[(size_t)(k0 + i) * N + n0 + tx];
    __syncthreads();
    #pragma unroll
    for (int i = ty; i < 32; i += 8) {
        int n = n0 + i, k = k0 + tx;
        float v = t[tx][i];
        __nv_bfloat16 hi, lo; split2(v, hi, lo);
        out[(size_t)n * 2 * K + k]     = hi;
        out[(size_t)n * 2 * K + K + k] = lo;
    }
}

// ---------------- LayerNorm -> split bf16 [row, 2D] -------------------------
__global__ void __launch_bounds__(256) ln_split_kernel(
    const float* __restrict__ x, const float* __restrict__ g,
    const float* __restrict__ beta, __nv_bfloat16* __restrict__ outs)
{
    int row = blockIdx.x;
    int tid = threadIdx.x;
    const float4* xr = reinterpret_cast<const float4*>(x + (size_t)row * DD);
    float4 v = xr[tid];
    float s  = v.x + v.y + v.z + v.w;
    float ss = v.x*v.x + v.y*v.y + v.z*v.z + v.w*v.w;
    #pragma unroll
    for (int o = 16; o > 0; o >>= 1) {
        s  += __shfl_xor_sync(0xffffffffu, s,  o);
        ss += __shfl_xor_sync(0xffffffffu, ss, o);
    }
    __shared__ float rs[8], rss[8];
    __shared__ float s_mu, s_rstd;
    int w = tid >> 5;
    if ((tid & 31) == 0) { rs[w] = s; rss[w] = ss; }
    __syncthreads();
    if (tid == 0) {
        float S = 0.f, SSum = 0.f;
        #pragma unroll
        for (int i = 0; i < 8; i++) { S += rs[i]; SSum += rss[i]; }
        float mu  = S * (1.0f / DD);
        float var = SSum * (1.0f / DD) - mu * mu;
        s_mu = mu; s_rstd = rsqrtf(var + 1e-6f);
    }
    __syncthreads();
    float mu = s_mu, rstd = s_rstd;
    float4 gv = reinterpret_cast<const float4*>(g)[tid];
    float4 bv = reinterpret_cast<const float4*>(beta)[tid];
    float o0 = (v.x - mu) * rstd * gv.x + bv.x;
    float o1 = (v.y - mu) * rstd * gv.y + bv.y;
    float o2 = (v.z - mu) * rstd * gv.z + bv.z;
    float o3 = (v.w - mu) * rstd * gv.w + bv.w;
    uint32_t h01, l01, h23, l23;
    packsplit2(o0, o1, h01, l01);
    packsplit2(o2, o3, h23, l23);
    uint32_t* dst = reinterpret_cast<uint32_t*>(outs + (size_t)row * 2 * DD);
    dst[tid * 2]           = h01;
    dst[tid * 2 + 1]       = h23;
    dst[DD/2 + tid * 2]     = l01;
    dst[DD/2 + tid * 2 + 1] = l23;
}

// ---------------- HMMA GEMM (3-stage pipeline): C = A2 @ B2^T + epilogue ----
// A2: [M, 2K] bf16 (hi|lo), B2: [N, 2K]. 3 passes: hi*hi + lo*hi + hi*lo.
// EPI 0: bias -> Cf ; EPI 1: bias+resid -> Cf ; EPI 2: gelu -> split Cs
#define GTS (128 * 40)   // halfs per stage tile
template<int EPI>
__global__ void __launch_bounds__(256) hmma_gemm_kernel(
    const __nv_bfloat16* __restrict__ A2, const __nv_bfloat16* __restrict__ B2,
    const float* __restrict__ bias, const float* __restrict__ resid,
    float* __restrict__ Cf, __nv_bfloat16* __restrict__ Cs, int N, int K)
{
    extern __shared__ __nv_bfloat16 gsm[];
    __nv_bfloat16* SA = gsm;            // [3][128][40]
    __nv_bfloat16* SB = gsm + 3 * GTS;  // [3][128][40]

    const int tid  = threadIdx.x;
    const int lane = tid & 31;
    const int wid  = tid >> 5;
    const int wm = wid >> 2, wn = wid & 3;     // 2 x 4 warp grid, warp tile 64x32
    const int rowM0 = blockIdx.y * 128;
    const int colN0 = blockIdx.x * 128;

    const int KC = K >> 5;
    const int NC = 3 * KC;
    const size_t strideA = 2 * (size_t)K;

    const int lrow = tid >> 2;
    const int lcol = (tid & 3) * 8;

    float acc[4][4][4];
    #pragma unroll
    for (int a = 0; a < 4; a++)
        #pragma unroll
        for (int b = 0; b < 4; b++)
            #pragma unroll
            for (int r = 0; r < 4; r++) acc[a][b][r] = 0.f;

    auto issue = [&](int c, int buf) {
        int p    = c / KC;
        int kc   = (c - p * KC) << 5;
        int aoff = (p == 1) ? K : 0;
        int boff = (p == 2) ? K : 0;
        __nv_bfloat16* At = SA + buf * GTS;
        __nv_bfloat16* Bt = SB + buf * GTS;
        #pragma unroll
        for (int it = 0; it < 2; it++) {
            int row = lrow + it * 64;
            cp16(At + row * 40 + lcol, A2 + (size_t)(rowM0 + row) * strideA + aoff + kc + lcol);
            cp16(Bt + row * 40 + lcol, B2 + (size_t)(colN0 + row) * strideA + boff + kc + lcol);
        }
    };

    issue(0, 0); CP_COMMIT();
    issue(1, 1); CP_COMMIT();

    for (int c = 0; c < NC; c++) {
        int buf = c % 3;
        if (c + 2 < NC) { issue(c + 2, (c + 2) % 3); CP_COMMIT(); CP_WAIT(2); }
        else if (c + 1 < NC) { CP_WAIT(1); }
        else { CP_WAIT(0); }
        __syncthreads();

        __nv_bfloat16* At = SA + buf * GTS;
        __nv_bfloat16* Bt = SB + buf * GTS;
        #pragma unroll
        for (int k16 = 0; k16 < 32; k16 += 16) {
            uint32_t af[4][4], bfr[4][2];
            #pragma unroll
            for (int im = 0; im < 4; im++)
                ldmA4(af[im], At + (wm * 64 + im * 16 + (lane & 15)) * 40
                                 + k16 + (lane >> 4) * 8);
            #pragma unroll
            for (int in_ = 0; in_ < 4; in_++) {
                uint32_t addr = smem_u32(Bt + (wn * 32 + in_ * 8 + (lane & 7)) * 40
                                            + k16 + ((lane >> 3) & 1) * 8);
                asm volatile("ldmatrix.sync.aligned.m8n8.x2.shared.b16 {%0,%1}, [%2];"
                    : "=r"(bfr[in_][0]), "=r"(bfr[in_][1]) : "r"(addr));
            }
            #pragma unroll
            for (int im = 0; im < 4; im++)
                #pragma unroll
                for (int in_ = 0; in_ < 4; in_++)
                    mma16816(acc[im][in_], af[im][0], af[im][1], af[im][2], af[im][3],
                             bfr[in_][0], bfr[in_][1]);
        }
        __syncthreads();
    }

    const int g = lane >> 2, t4 = lane & 3;
    #pragma unroll
    for (int im = 0; im < 4; im++) {
        #pragma unroll
        for (int half = 0; half < 2; half++) {
            int row = rowM0 + wm * 64 + im * 16 + g + half * 8;
            #pragma unroll
            for (int in_ = 0; in_ < 4; in_++) {
                int col = colN0 + wn * 32 + in_ * 8 + t4 * 2;
                float v0 = acc[im][in_][half * 2]     + bias[col];
                float v1 = acc[im][in_][half * 2 + 1] + bias[col + 1];
                if (EPI == 1) {
                    v0 += resid[(size_t)row * N + col];
                    v1 += resid[(size_t)row * N + col + 1];
                }
                if (EPI == 2) {
                    v0 = 0.5f * v0 * (1.0f + erff(v0 * 0.70710678118f));
                    v1 = 0.5f * v1 * (1.0f + erff(v1 * 0.70710678118f));
                    uint32_t hp, lp;
                    packsplit2(v0, v1, hp, lp);
                    uint32_t* dst = reinterpret_cast<uint32_t*>(Cs + (size_t)row * 2 * N + col);
                    dst[0]     = hp;
                    dst[N / 2] = lp;
                } else {
                    float2 o; o.x = v0; o.y = v1;
                    *reinterpret_cast<float2*>(&Cf[(size_t)row * N + col]) = o;
                }
            }
        }
    }
}

// ---------------- qkv prep: L2-norm q,k (+scale into q) and split to [b,h,s,128]
__global__ void __launch_bounds__(256) qkvprep_kernel(
    const float* __restrict__ q, const float* __restrict__ k, const float* __restrict__ v,
    const float* __restrict__ logit_scale,
    __nv_bfloat16* __restrict__ qs, __nv_bfloat16* __restrict__ ks,
    __nv_bfloat16* __restrict__ vs)
{
    int gid  = blockIdx.x * blockDim.x + threadIdx.x;
    int wrp  = gid >> 5;
    int lane = gid & 31;
    int token = wrp >> 4;     // / HH   (m index = b*S + s)
    int h     = wrp & 15;
    float scale = __expf(fminf(logit_scale[h], LOG_MAX_F));

    const float* qp = q + (size_t)token * DD + h * HD;
    const float* kp = k + (size_t)token * DD + h * HD;
    const float* vp = v + (size_t)token * DD + h * HD;
    float2 qv = reinterpret_cast<const float2*>(qp)[lane];
    float2 kv = reinterpret_cast<const float2*>(kp)[lane];
    float2 vv = reinterpret_cast<const float2*>(vp)[lane];
    float sq = qv.x * qv.x + qv.y * qv.y;
    float sk = kv.x * kv.x + kv.y * kv.y;
    #pragma unroll
    for (int o = 16; o > 0; o >>= 1) {
        sq += __shfl_xor_sync(0xffffffffu, sq, o);
        sk += __shfl_xor_sync(0xffffffffu, sk, o);
    }
    float iq = scale / fmaxf(sqrtf(sq), 1e-12f);
    float ik = 1.0f  / fmaxf(sqrtf(sk), 1e-12f);

    int b = token >> 11, s = token & (SS - 1);
    size_t drow = ((size_t)(b * HH + h) * SS + s) * 128;
    uint32_t hi, lo;
    uint32_t* qd = reinterpret_cast<uint32_t*>(qs + drow);
    packsplit2(qv.x * iq, qv.y * iq, hi, lo);
    qd[lane] = hi; qd[32 + lane] = lo;
    uint32_t* kd = reinterpret_cast<uint32_t*>(ks + drow);
    packsplit2(kv.x * ik, kv.y * ik, hi, lo);
    kd[lane] = hi; kd[32 + lane] = lo;
    uint32_t* vd = reinterpret_cast<uint32_t*>(vs + drow);
    packsplit2(vv.x, vv.y, hi, lo);
    vd[lane] = hi; vd[32 + lane] = lo;
}

// ---------------- flash attention, HMMA split-bf16 --------------------------
// 128 queries / CTA, 8 warps (each 16 rows), 64-key tiles, online softmax.
#define FP 72
__global__ void __launch_bounds__(256) flash_tc_kernel(
    const __nv_bfloat16* __restrict__ qs, const __nv_bfloat16* __restrict__ ks,
    const __nv_bfloat16* __restrict__ vs, __nv_bfloat16* __restrict__ ctxs)
{
    extern __shared__ __nv_bfloat16 fsm[];
    __nv_bfloat16* Qh = fsm;                // [128][72]
    __nv_bfloat16* Ql = Qh + 128 * FP;
    __nv_bfloat16* Kh = Ql + 128 * FP;      // [64][72]
    __nv_bfloat16* Kl = Kh + 64 * FP;
    __nv_bfloat16* Vh = Kl + 64 * FP;
    __nv_bfloat16* Vl = Vh + 64 * FP;

    const int tid = threadIdx.x, lane = tid & 31, wid = tid >> 5;
    const int b = blockIdx.z, h = blockIdx.y, q0 = blockIdx.x * 128;
    const __nv_bfloat16* gq = qs + ((size_t)(b * HH + h) * SS + q0) * 128;
    const __nv_bfloat16* gk = ks + ((size_t)(b * HH + h) * SS) * 128;
    const __nv_bfloat16* gv = vs + ((size_t)(b * HH + h) * SS) * 128;

    // Q: 128 rows x 16 chunks (16B)
    #pragma unroll
    for (int t = 0; t < 8; t++) {
        int c = t * 256 + tid;
        int row = c >> 4, sub = c & 15;
        __nv_bfloat16* dst = (sub < 8) ? (Qh + row * FP + sub * 8)
                                       : (Ql + row * FP + (sub - 8) * 8);
        cp16(dst, gq + row * 128 + sub * 8);
    }
    CP_COMMIT();

    auto loadKV = [&](__nv_bfloat16* Ph, __nv_bfloat16* Pl,
                      const __nv_bfloat16* src, int kv0) {
        #pragma unroll
        for (int t = 0; t < 4; t++) {
            int c = t * 256 + tid;
            int row = c >> 4, sub = c & 15;
            __nv_bfloat16* dst = (sub < 8) ? (Ph + row * FP + sub * 8)
                                           : (Pl + row * FP + (sub - 8) * 8);
            cp16(dst, src + (size_t)(kv0 + row) * 128 + sub * 8);
        }
    };
    loadKV(Kh, Kl, gk, 0); CP_COMMIT();
    loadKV(Vh, Vl, gv, 0); CP_COMMIT();

    const int g = lane >> 2, t4 = lane & 3;
    float m0 = -1e30f, m1 = -1e30f, l0 = 0.f, l1 = 0.f;
    float o[8][4];
    #pragma unroll
    for (int j = 0; j < 8; j++)
        #pragma unroll
        for (int r = 0; r < 4; r++) o[j][r] = 0.f;

    const int NT = SS / 64;
    for (int t = 0; t < NT; t++) {
        CP_WAIT(1);            // K(t) ready (V(t) may be pending)
        __syncthreads();

        // ---- S = Qh*Kh + Ql*Kh + Qh*Kl ----
        float s[8][4];
        #pragma unroll
        for (int j = 0; j < 8; j++)
            #pragma unroll
            for (int r = 0; r < 4; r++) s[j][r] = 0.f;

        #pragma unroll
        for (int k16 = 0; k16 < 64; k16 += 16) {
            uint32_t Ah[4], Al[4];
            int arow = wid * 16 + (lane & 15);
            int acol = k16 + (lane >> 4) * 8;
            ldmA4(Ah, Qh + arow * FP + acol);
            ldmA4(Al, Ql + arow * FP + acol);
            #pragma unroll
            for (int nn = 0; nn < 4; nn++) {
                int n0 = nn * 16;
                int brow = n0 + (lane & 7) + ((lane >> 4) ? 8 : 0);
                int bcol = k16 + ((lane >> 3) & 1) * 8;
                uint32_t Bh[4], Bl[4];
                ldmA4(Bh, Kh + brow * FP + bcol);
                mma16816(s[2*nn],   Ah[0], Ah[1], Ah[2], Ah[3], Bh[0], Bh[1]);
                mma16816(s[2*nn+1], Ah[0], Ah[1], Ah[2], Ah[3], Bh[2], Bh[3]);
                mma16816(s[2*nn],   Al[0], Al[1], Al[2], Al[3], Bh[0], Bh[1]);
                mma16816(s[2*nn+1], Al[0], Al[1], Al[2], Al[3], Bh[2], Bh[3]);
                ldmA4(Bl, Kl + brow * FP + bcol);
                mma16816(s[2*nn],   Ah[0], Ah[1], Ah[2], Ah[3], Bl[0], Bl[1]);
                mma16816(s[2*nn+1], Ah[0], Ah[1], Ah[2], Ah[3], Bl[2], Bl[3]);
            }
        }
        __syncthreads();       // done reading K
        if (t + 1 < NT) { loadKV(Kh, Kl, gk, (t + 1) * 64); CP_COMMIT(); CP_WAIT(1); }
        else           { CP_WAIT(0); }
        // V(t) now arrived (register-only work until barrier below)

        // ---- online softmax ----
        float mx0 = -1e30f, mx1 = -1e30f;
        #pragma unroll
        for (int j = 0; j < 8; j++) {
            mx0 = fmaxf(mx0, fmaxf(s[j][0], s[j][1]));
            mx1 = fmaxf(mx1, fmaxf(s[j][2], s[j][3]));
        }
        mx0 = fmaxf(mx0, __shfl_xor_sync(0xffffffffu, mx0, 1));
        mx0 = fmaxf(mx0, __shfl_xor_sync(0xffffffffu, mx0, 2));
        mx1 = fmaxf(mx1, __shfl_xor_sync(0xffffffffu, mx1, 1));
        mx1 = fmaxf(mx1, __shfl_xor_sync(0xffffffffu, mx1, 2));
        float mn0 = fmaxf(m0, mx0), mn1 = fmaxf(m1, mx1);
        float a0 = __expf(m0 - mn0), a1 = __expf(m1 - mn1);
        float sum0 = 0.f, sum1 = 0.f;
        #pragma unroll
        for (int j = 0; j < 8; j++) {
            s[j][0] = __expf(s[j][0] - mn0);
            s[j][1] = __expf(s[j][1] - mn0);
            s[j][2] = __expf(s[j][2] - mn1);
            s[j][3] = __expf(s[j][3] - mn1);
            sum0 += s[j][0] + s[j][1];
            sum1 += s[j][2] + s[j][3];
        }
        sum0 += __shfl_xor_sync(0xffffffffu, sum0, 1);
        sum0 += __shfl_xor_sync(0xffffffffu, sum0, 2);
        sum1 += __shfl_xor_sync(0xffffffffu, sum1, 1);
        sum1 += __shfl_xor_sync(0xffffffffu, sum1, 2);
        l0 = l0 * a0 + sum0; l1 = l1 * a1 + sum1;
        m0 = mn0; m1 = mn1;
        #pragma unroll
        for (int j = 0; j < 8; j++) {
            o[j][0] *= a0; o[j][1] *= a0;
            o[j][2] *= a1; o[j][3] *= a1;
        }

        // pack P fragments (hi/lo split)
        uint32_t aPh[4][4], aPl[4][4];
        #pragma unroll
        for (int j = 0; j < 4; j++) {
            packsplit2(s[2*j][0],   s[2*j][1],   aPh[j][0], aPl[j][0]);
            packsplit2(s[2*j][2],   s[2*j][3],   aPh[j][1], aPl[j][1]);
            packsplit2(s[2*j+1][0], s[2*j+1][1], aPh[j][2], aPl[j][2]);
            packsplit2(s[2*j+1][2], s[2*j+1][3], aPh[j][3], aPl[j][3]);
        }

        __syncthreads();       // V tile visible to all threads

        // ---- O += Ph*Vh + Pl*Vh + Ph*Vl ----
        #pragma unroll
        for (int j = 0; j < 4; j++) {
            int k0 = j * 16;
            int vrow = k0 + (lane & 7) + (((lane >> 3) & 1) ? 8 : 0);
            #pragma unroll
            for (int nn = 0; nn < 4; nn++) {
                int n0 = nn * 16 + ((lane >> 4) ? 8 : 0);
                uint32_t Bv[4], Bl2[4];
                ldmT4(Bv, Vh + vrow * FP + n0);
                mma16816(o[2*nn],   aPh[j][0], aPh[j][1], aPh[j][2], aPh[j][3], Bv[0], Bv[1]);
                mma16816(o[2*nn+1], aPh[j][0], aPh[j][1], aPh[j][2], aPh[j][3], Bv[2], Bv[3]);
                mma16816(o[2*nn],   aPl[j][0], aPl[j][1], aPl[j][2], aPl[j][3], Bv[0], Bv[1]);
                mma16816(o[2*nn+1], aPl[j][0], aPl[j][1], aPl[j][2], aPl[j][3], Bv[2], Bv[3]);
                ldmT4(Bl2, Vl + vrow * FP + n0);
                mma16816(o[2*nn],   aPh[j][0], aPh[j][1], aPh[j][2], aPh[j][3], Bl2[0], Bl2[1]);
                mma16816(o[2*nn+1], aPh[j][0], aPh[j][1], aPh[j][2], aPh[j][3], Bl2[2], Bl2[3]);
            }
        }
        __syncthreads();       // done reading V
        if (t + 1 < NT) { loadKV(Vh, Vl, gv, (t + 1) * 64); CP_COMMIT(); }
    }

    // ---- finalize: O /= l, split-write to ctxs [m, 2D] ----
    float inv0 = 1.0f / l0, inv1 = 1.0f / l1;
    int row0 = (b * SS) + q0 + wid * 16 + g;
    int row1 = row0 + 8;
    #pragma unroll
    for (int nt = 0; nt < 8; nt++) {
        int col = h * HD + nt * 8 + t4 * 2;
        uint32_t hp, lp;
        packsplit2(o[nt][0] * inv0, o[nt][1] * inv0, hp, lp);
        uint32_t* d0 = reinterpret_cast<uint32_t*>(ctxs + (size_t)row0 * 2 * DD + col);
        d0[0] = hp; d0[DD / 2] = lp;
        packsplit2(o[nt][2] * inv1, o[nt][3] * inv1, hp, lp);
        uint32_t* d1 = reinterpret_cast<uint32_t*>(ctxs + (size_t)row1 * 2 * DD + col);
        d1[0] = hp; d1[DD / 2] = lp;
    }
}

// ---------------- driver ----------------
#define GEMM_SMEM (6 * GTS * 2)          // 61440 B
#define FLASH_SMEM ((128*FP*2 + 64*FP*4) * 2)  // 73728 B

extern "C" void kernel_launch(void* const* d_in, const int* in_sizes, int n_in,
                              void* d_out, int out_size)
{
    const float* x     = (const float*)d_in[0];
    const float* wq    = (const float*)d_in[1];
    const float* bq    = (const float*)d_in[2];
    const float* wk    = (const float*)d_in[3];
    const float* bk    = (const float*)d_in[4];
    const float* wv    = (const float*)d_in[5];
    const float* bv    = (const float*)d_in[6];
    const float* wo    = (const float*)d_in[7];
    const float* bo    = (const float*)d_in[8];
    const float* w1    = (const float*)d_in[9];
    const float* b1    = (const float*)d_in[10];
    const float* w2    = (const float*)d_in[11];
    const float* b2    = (const float*)d_in[12];
    const float* ln1_g = (const float*)d_in[13];
    const float* ln1_b = (const float*)d_in[14];
    const float* ln2_g = (const float*)d_in[15];
    const float* ln2_b = (const float*)d_in[16];
    const float* lscal = (const float*)d_in[17];
    float* out = (float*)d_out;

    __nv_bfloat16 *xns, *ctxs, *h1s, *wqs, *wks, *wvs, *wos, *w1s, *w2s;
    __nv_bfloat16 *qsb, *ksb, *vsb;
    float *qf, *kf, *vf, *x2f;
    cudaGetSymbolAddress((void**)&xns,  g_xns);
    cudaGetSymbolAddress((void**)&ctxs, g_ctxs);
    cudaGetSymbolAddress((void**)&h1s,  g_h1s);
    cudaGetSymbolAddress((void**)&wqs,  g_wqs);
    cudaGetSymbolAddress((void**)&wks,  g_wks);
    cudaGetSymbolAddress((void**)&wvs,  g_wvs);
    cudaGetSymbolAddress((void**)&wos,  g_wos);
    cudaGetSymbolAddress((void**)&w1s,  g_w1s);
    cudaGetSymbolAddress((void**)&w2s,  g_w2s);
    cudaGetSymbolAddress((void**)&qf,   g_q);
    cudaGetSymbolAddress((void**)&kf,   g_k);
    cudaGetSymbolAddress((void**)&vf,   g_v);
    cudaGetSymbolAddress((void**)&x2f,  g_x2);
    cudaGetSymbolAddress((void**)&qsb,  g_qsb);
    cudaGetSymbolAddress((void**)&ksb,  g_ksb);
    cudaGetSymbolAddress((void**)&vsb,  g_vsb);

    cudaFuncSetAttribute(hmma_gemm_kernel<0>, cudaFuncAttributeMaxDynamicSharedMemorySize, GEMM_SMEM);
    cudaFuncSetAttribute(hmma_gemm_kernel<1>, cudaFuncAttributeMaxDynamicSharedMemorySize, GEMM_SMEM);
    cudaFuncSetAttribute(hmma_gemm_kernel<2>, cudaFuncAttributeMaxDynamicSharedMemorySize, GEMM_SMEM);
    cudaFuncSetAttribute(flash_tc_kernel, cudaFuncAttributeMaxDynamicSharedMemorySize, FLASH_SMEM);

    dim3 wb(32, 8);
    wsplit_kernel<<<dim3(DD/32,  DD/32),  wb>>>(wq, wqs, DD,   DD);
    wsplit_kernel<<<dim3(DD/32,  DD/32),  wb>>>(wk, wks, DD,   DD);
    wsplit_kernel<<<dim3(DD/32,  DD/32),  wb>>>(wv, wvs, DD,   DD);
    wsplit_kernel<<<dim3(DD/32,  DD/32),  wb>>>(wo, wos, DD,   DD);
    wsplit_kernel<<<dim3(MLPD/32, DD/32), wb>>>(w1, w1s, DD,   MLPD);
    wsplit_kernel<<<dim3(DD/32, MLPD/32), wb>>>(w2, w2s, MLPD, DD);

    ln_split_kernel<<<MM, 256>>>(x, ln1_g, ln1_b, xns);

    dim3 gQKV(DD / 128, MM / 128);     // (8, 32)
    dim3 gMLP1(MLPD / 128, MM / 128);  // (32, 32)

    hmma_gemm_kernel<0><<<gQKV, 256, GEMM_SMEM>>>(xns, wqs, bq, nullptr, qf, nullptr, DD, DD);
    hmma_gemm_kernel<0><<<gQKV, 256, GEMM_SMEM>>>(xns, wks, bk, nullptr, kf, nullptr, DD, DD);
    hmma_gemm_kernel<0><<<gQKV, 256, GEMM_SMEM>>>(xns, wvs, bv, nullptr, vf, nullptr, DD, DD);

    qkvprep_kernel<<<(MM * HH * 32) / 256, 256>>>(qf, kf, vf, lscal, qsb, ksb, vsb);

    flash_tc_kernel<<<dim3(SS / 128, HH, BB), 256, FLASH_SMEM>>>(qsb, ksb, vsb, ctxs);

    hmma_gemm_kernel<1><<<gQKV, 256, GEMM_SMEM>>>(ctxs, wos, bo, x, x2f, nullptr, DD, DD);

    ln_split_kernel<<<MM, 256>>>(x2f, ln2_g, ln2_b, xns);

    hmma_gemm_kernel<2><<<gMLP1, 256, GEMM_SMEM>>>(xns, w1s, b1, nullptr, nullptr, h1s, MLPD, DD);

    hmma_gemm_kernel<1><<<gQKV, 256, GEMM_SMEM>>>(h1s, w2s, b2, x2f, out, nullptr, DD, MLPD);
}

// round 5
// speedup vs baseline: 2.5418x; 1.1042x over previous
#include <cuda_runtime.h>
#include <cuda_bf16.h>
#include <math.h>
#include <stdint.h>

// ---------------- problem constants ----------------
#define BB    2
#define SS    2048
#define DD    1024
#define HH    16
#define HD    64
#define MLPD  4096
#define MM    (BB*SS)          // 4096 rows
#define LOG_MAX_F 4.6051702f   // log(1/0.01)

// ---------------- scratch (device globals; no allocs allowed) ----------------
__device__ __align__(16) __nv_bfloat16 g_xns [(size_t)MM * 2 * DD];
__device__ __align__(16) __nv_bfloat16 g_ctxs[(size_t)MM * 2 * DD];
__device__ __align__(16) __nv_bfloat16 g_h1s [(size_t)MM * 2 * MLPD];
__device__ float g_qkv[(size_t)MM * 3 * DD];   // fused QKV output
__device__ float g_x2 [MM*DD];
// per-head split q/k/v for flash: [b,h,s, (hi64|lo64)]
__device__ __align__(16) __nv_bfloat16 g_qsb[(size_t)BB*HH*SS*128];
__device__ __align__(16) __nv_bfloat16 g_ksb[(size_t)BB*HH*SS*128];
__device__ __align__(16) __nv_bfloat16 g_vsb[(size_t)BB*HH*SS*128];
// split+transposed weights: [N, 2K] bf16
__device__ __align__(16) __nv_bfloat16 g_wqkvs[(size_t)(3*DD) * 2 * DD];
__device__ __align__(16) __nv_bfloat16 g_wos  [(size_t)DD * 2 * DD];
__device__ __align__(16) __nv_bfloat16 g_w1s  [(size_t)MLPD * 2 * DD];
__device__ __align__(16) __nv_bfloat16 g_w2s  [(size_t)DD * 2 * MLPD];
__device__ float g_bqkv[3*DD];

__device__ __forceinline__ uint32_t smem_u32(const void* p) {
    return (uint32_t)__cvta_generic_to_shared(p);
}
__device__ __forceinline__ void split2(float v, __nv_bfloat16& hi, __nv_bfloat16& lo) {
    hi = __float2bfloat16(v);
    lo = __float2bfloat16(v - __bfloat162float(hi));
}
__device__ __forceinline__ void cp16(void* dst, const void* src) {
    asm volatile("cp.async.cg.shared.global [%0], [%1], 16;" :: "r"(smem_u32(dst)), "l"(src));
}
#define CP_COMMIT() asm volatile("cp.async.commit_group;" ::: "memory")
#define CP_WAIT(n)  asm volatile("cp.async.wait_group %0;" :: "n"(n) : "memory")

__device__ __forceinline__ void ldmA4(uint32_t* r, const void* p) {
    asm volatile("ldmatrix.sync.aligned.m8n8.x4.shared.b16 {%0,%1,%2,%3}, [%4];"
        : "=r"(r[0]), "=r"(r[1]), "=r"(r[2]), "=r"(r[3]) : "r"(smem_u32(p)));
}
__device__ __forceinline__ void ldmT4(uint32_t* r, const void* p) {
    asm volatile("ldmatrix.sync.aligned.m8n8.x4.trans.shared.b16 {%0,%1,%2,%3}, [%4];"
        : "=r"(r[0]), "=r"(r[1]), "=r"(r[2]), "=r"(r[3]) : "r"(smem_u32(p)));
}
__device__ __forceinline__ void mma16816(float* c, uint32_t a0, uint32_t a1, uint32_t a2,
                                         uint32_t a3, uint32_t b0, uint32_t b1) {
    asm volatile("mma.sync.aligned.m16n8k16.row.col.f32.bf16.bf16.f32 "
        "{%0,%1,%2,%3}, {%4,%5,%6,%7}, {%8,%9}, {%0,%1,%2,%3};"
        : "+f"(c[0]), "+f"(c[1]), "+f"(c[2]), "+f"(c[3])
        : "r"(a0), "r"(a1), "r"(a2), "r"(a3), "r"(b0), "r"(b1));
}
__device__ __forceinline__ void packsplit2(float x, float y, uint32_t& hi, uint32_t& lo) {
    __nv_bfloat16 hx, lx, hy, ly;
    split2(x, hx, lx); split2(y, hy, ly);
    __nv_bfloat162 hp; hp.x = hx; hp.y = hy;
    __nv_bfloat162 lp; lp.x = lx; lp.y = ly;
    hi = *reinterpret_cast<uint32_t*>(&hp);
    lo = *reinterpret_cast<uint32_t*>(&lp);
}

// ---------------- weight transpose + split: W[K,N] f32 -> out[N,2K] bf16 ----
__global__ void __launch_bounds__(256) wsplit_kernel(
    const float* __restrict__ W, __nv_bfloat16* __restrict__ out, int K, int N)
{
    __shared__ float t[32][33];
    int n0 = blockIdx.x * 32, k0 = blockIdx.y * 32;
    int tx = threadIdx.x, ty = threadIdx.y;
    #pragma unroll
    for (int i = ty; i < 32; i += 8)
        t[i][tx] = W[(size_t)(k0 + i) * N + n0 + tx];
    __syncthreads();
    #pragma unroll
    for (int i = ty; i < 32; i += 8) {
        int n = n0 + i, k = k0 + tx;
        float v = t[tx][i];
        __nv_bfloat16 hi, lo; split2(v, hi, lo);
        out[(size_t)n * 2 * K + k]     = hi;
        out[(size_t)n * 2 * K + K + k] = lo;
    }
}

// ---------------- pack qkv bias ----------------------------------------------
__global__ void packb_kernel(const float* __restrict__ bq, const float* __restrict__ bk,
                             const float* __restrict__ bv, float* __restrict__ out)
{
    int i = blockIdx.x * blockDim.x + threadIdx.x;
    if (i < DD)            out[i] = bq[i];
    else if (i < 2 * DD)   out[i] = bk[i - DD];
    else if (i < 3 * DD)   out[i] = bv[i - 2 * DD];
}

// ---------------- LayerNorm -> split bf16 [row, 2D] -------------------------
__global__ void __launch_bounds__(256) ln_split_kernel(
    const float* __restrict__ x, const float* __restrict__ g,
    const float* __restrict__ beta, __nv_bfloat16* __restrict__ outs)
{
    int row = blockIdx.x;
    int tid = threadIdx.x;
    const float4* xr = reinterpret_cast<const float4*>(x + (size_t)row * DD);
    float4 v = xr[tid];
    float s  = v.x + v.y + v.z + v.w;
    float ss = v.x*v.x + v.y*v.y + v.z*v.z + v.w*v.w;
    #pragma unroll
    for (int o = 16; o > 0; o >>= 1) {
        s  += __shfl_xor_sync(0xffffffffu, s,  o);
        ss += __shfl_xor_sync(0xffffffffu, ss, o);
    }
    __shared__ float rs[8], rss[8];
    __shared__ float s_mu, s_rstd;
    int w = tid >> 5;
    if ((tid & 31) == 0) { rs[w] = s; rss[w] = ss; }
    __syncthreads();
    if (tid == 0) {
        float S = 0.f, SSum = 0.f;
        #pragma unroll
        for (int i = 0; i < 8; i++) { S += rs[i]; SSum += rss[i]; }
        float mu  = S * (1.0f / DD);
        float var = SSum * (1.0f / DD) - mu * mu;
        s_mu = mu; s_rstd = rsqrtf(var + 1e-6f);
    }
    __syncthreads();
    float mu = s_mu, rstd = s_rstd;
    float4 gv = reinterpret_cast<const float4*>(g)[tid];
    float4 bv = reinterpret_cast<const float4*>(beta)[tid];
    float o0 = (v.x - mu) * rstd * gv.x + bv.x;
    float o1 = (v.y - mu) * rstd * gv.y + bv.y;
    float o2 = (v.z - mu) * rstd * gv.z + bv.z;
    float o3 = (v.w - mu) * rstd * gv.w + bv.w;
    uint32_t h01, l01, h23, l23;
    packsplit2(o0, o1, h01, l01);
    packsplit2(o2, o3, h23, l23);
    uint32_t* dst = reinterpret_cast<uint32_t*>(outs + (size_t)row * 2 * DD);
    dst[tid * 2]           = h01;
    dst[tid * 2 + 1]       = h23;
    dst[DD/2 + tid * 2]     = l01;
    dst[DD/2 + tid * 2 + 1] = l23;
}

// ---------------- HMMA GEMM: hi/lo tiles resident once, 3 MMA terms ---------
// A2: [M, 2K] bf16 (hi|lo), B2: [N, 2K]. acc = Ah*Bh + Al*Bh + Ah*Bl.
// EPI 0: bias -> Cf ; EPI 1: bias+resid -> Cf ; EPI 2: gelu -> split Cs
#define TILE (128 * 40)
#define GST  (4 * TILE)      // halfs per stage: Ahi, Alo, Bhi, Blo
template<int EPI>
__global__ void __launch_bounds__(256) hmma_gemm_kernel(
    const __nv_bfloat16* __restrict__ A2, const __nv_bfloat16* __restrict__ B2,
    const float* __restrict__ bias, const float* __restrict__ resid,
    float* __restrict__ Cf, __nv_bfloat16* __restrict__ Cs, int N, int K)
{
    extern __shared__ __nv_bfloat16 gsm[];

    const int tid  = threadIdx.x;
    const int lane = tid & 31;
    const int wid  = tid >> 5;
    const int wm = wid >> 2, wn = wid & 3;     // 2 x 4 warp grid, warp tile 64x32
    const int rowM0 = blockIdx.y * 128;
    const int colN0 = blockIdx.x * 128;

    const int KC = K >> 5;                     // 32-wide k-chunks
    const size_t strideA = 2 * (size_t)K;

    const int lrow = tid >> 2;
    const int lcol = (tid & 3) * 8;

    float acc[4][4][4];
    #pragma unroll
    for (int a = 0; a < 4; a++)
        #pragma unroll
        for (int b = 0; b < 4; b++)
            #pragma unroll
            for (int r = 0; r < 4; r++) acc[a][b][r] = 0.f;

    auto issue = [&](int c, int buf) {
        int kc = c << 5;
        __nv_bfloat16* Sg = gsm + buf * GST;
        #pragma unroll
        for (int it = 0; it < 2; it++) {
            int row = lrow + it * 64;
            const __nv_bfloat16* Ar = A2 + (size_t)(rowM0 + row) * strideA + kc + lcol;
            const __nv_bfloat16* Br = B2 + (size_t)(colN0 + row) * strideA + kc + lcol;
            cp16(Sg + 0 * TILE + row * 40 + lcol, Ar);
            cp16(Sg + 1 * TILE + row * 40 + lcol, Ar + K);
            cp16(Sg + 2 * TILE + row * 40 + lcol, Br);
            cp16(Sg + 3 * TILE + row * 40 + lcol, Br + K);
        }
    };

    issue(0, 0); CP_COMMIT();
    issue(1, 1); CP_COMMIT();

    for (int c = 0; c < KC; c++) {
        int buf = c % 3;
        if (c + 2 < KC) { issue(c + 2, (c + 2) % 3); CP_COMMIT(); CP_WAIT(2); }
        else if (c + 1 < KC) { CP_WAIT(1); }
        else { CP_WAIT(0); }
        __syncthreads();

        __nv_bfloat16* Sg = gsm + buf * GST;
        __nv_bfloat16* Ahi = Sg;
        __nv_bfloat16* Alo = Sg + TILE;
        __nv_bfloat16* Bhi = Sg + 2 * TILE;
        __nv_bfloat16* Blo = Sg + 3 * TILE;

        #pragma unroll
        for (int k16 = 0; k16 < 32; k16 += 16) {
            uint32_t Ah[4][4], Al[4][4], Bh[2][4], Bl[2][4];
            const int arow = wm * 64 + (lane & 15);
            const int acol = k16 + (lane >> 4) * 8;
            #pragma unroll
            for (int im = 0; im < 4; im++) {
                ldmA4(Ah[im], Ahi + (arow + im * 16) * 40 + acol);
                ldmA4(Al[im], Alo + (arow + im * 16) * 40 + acol);
            }
            const int brbase = wn * 32 + (lane & 7) + ((lane >> 4) ? 8 : 0);
            const int bcol = k16 + ((lane >> 3) & 1) * 8;
            #pragma unroll
            for (int nb = 0; nb < 2; nb++) {
                ldmA4(Bh[nb], Bhi + (brbase + nb * 16) * 40 + bcol);
                ldmA4(Bl[nb], Blo + (brbase + nb * 16) * 40 + bcol);
            }
            #pragma unroll
            for (int im = 0; im < 4; im++)
                #pragma unroll
                for (int nb = 0; nb < 2; nb++) {
                    float* c0 = acc[im][2 * nb];
                    float* c1 = acc[im][2 * nb + 1];
                    mma16816(c0, Ah[im][0], Ah[im][1], Ah[im][2], Ah[im][3], Bh[nb][0], Bh[nb][1]);
                    mma16816(c1, Ah[im][0], Ah[im][1], Ah[im][2], Ah[im][3], Bh[nb][2], Bh[nb][3]);
                    mma16816(c0, Al[im][0], Al[im][1], Al[im][2], Al[im][3], Bh[nb][0], Bh[nb][1]);
                    mma16816(c1, Al[im][0], Al[im][1], Al[im][2], Al[im][3], Bh[nb][2], Bh[nb][3]);
                    mma16816(c0, Ah[im][0], Ah[im][1], Ah[im][2], Ah[im][3], Bl[nb][0], Bl[nb][1]);
                    mma16816(c1, Ah[im][0], Ah[im][1], Ah[im][2], Ah[im][3], Bl[nb][2], Bl[nb][3]);
                }
        }
        __syncthreads();
    }

    // epilogue: acc[im][j] covers cols wn*32 + (j>>1)*16 + (j&1)*8
    const int g = lane >> 2, t4 = lane & 3;
    #pragma unroll
    for (int im = 0; im < 4; im++) {
        #pragma unroll
        for (int half = 0; half < 2; half++) {
            int row = rowM0 + wm * 64 + im * 16 + g + half * 8;
            #pragma unroll
            for (int j = 0; j < 4; j++) {
                int col = colN0 + wn * 32 + (j >> 1) * 16 + (j & 1) * 8 + t4 * 2;
                float v0 = acc[im][j][half * 2]     + bias[col];
                float v1 = acc[im][j][half * 2 + 1] + bias[col + 1];
                if (EPI == 1) {
                    v0 += resid[(size_t)row * N + col];
                    v1 += resid[(size_t)row * N + col + 1];
                }
                if (EPI == 2) {
                    v0 = 0.5f * v0 * (1.0f + erff(v0 * 0.70710678118f));
                    v1 = 0.5f * v1 * (1.0f + erff(v1 * 0.70710678118f));
                    uint32_t hp, lp;
                    packsplit2(v0, v1, hp, lp);
                    uint32_t* dst = reinterpret_cast<uint32_t*>(Cs + (size_t)row * 2 * N + col);
                    dst[0]     = hp;
                    dst[N / 2] = lp;
                } else {
                    float2 o; o.x = v0; o.y = v1;
                    *reinterpret_cast<float2*>(&Cf[(size_t)row * N + col]) = o;
                }
            }
        }
    }
}

// ---------------- qkv prep: L2-norm q,k (+scale into q), split to [b,h,s,128]
__global__ void __launch_bounds__(256) qkvprep_kernel(
    const float* __restrict__ qkv, const float* __restrict__ logit_scale,
    __nv_bfloat16* __restrict__ qs, __nv_bfloat16* __restrict__ ks,
    __nv_bfloat16* __restrict__ vs)
{
    int gid  = blockIdx.x * blockDim.x + threadIdx.x;
    int wrp  = gid >> 5;
    int lane = gid & 31;
    int token = wrp >> 4;
    int h     = wrp & 15;
    float scale = __expf(fminf(logit_scale[h], LOG_MAX_F));

    const float* base = qkv + (size_t)token * (3 * DD) + h * HD;
    float2 qv = reinterpret_cast<const float2*>(base)[lane];
    float2 kv = reinterpret_cast<const float2*>(base + DD)[lane];
    float2 vv = reinterpret_cast<const float2*>(base + 2 * DD)[lane];
    float sq = qv.x * qv.x + qv.y * qv.y;
    float sk = kv.x * kv.x + kv.y * kv.y;
    #pragma unroll
    for (int o = 16; o > 0; o >>= 1) {
        sq += __shfl_xor_sync(0xffffffffu, sq, o);
        sk += __shfl_xor_sync(0xffffffffu, sk, o);
    }
    float iq = scale / fmaxf(sqrtf(sq), 1e-12f);
    float ik = 1.0f  / fmaxf(sqrtf(sk), 1e-12f);

    int b = token >> 11, s = token & (SS - 1);
    size_t drow = ((size_t)(b * HH + h) * SS + s) * 128;
    uint32_t hi, lo;
    uint32_t* qd = reinterpret_cast<uint32_t*>(qs + drow);
    packsplit2(qv.x * iq, qv.y * iq, hi, lo);
    qd[lane] = hi; qd[32 + lane] = lo;
    uint32_t* kd = reinterpret_cast<uint32_t*>(ks + drow);
    packsplit2(kv.x * ik, kv.y * ik, hi, lo);
    kd[lane] = hi; kd[32 + lane] = lo;
    uint32_t* vd = reinterpret_cast<uint32_t*>(vs + drow);
    packsplit2(vv.x, vv.y, hi, lo);
    vd[lane] = hi; vd[32 + lane] = lo;
}

// ---------------- flash attention, HMMA split-bf16 --------------------------
#define FP 72
__global__ void __launch_bounds__(256) flash_tc_kernel(
    const __nv_bfloat16* __restrict__ qs, const __nv_bfloat16* __restrict__ ks,
    const __nv_bfloat16* __restrict__ vs, __nv_bfloat16* __restrict__ ctxs)
{
    extern __shared__ __nv_bfloat16 fsm[];
    __nv_bfloat16* Qh = fsm;                // [128][72]
    __nv_bfloat16* Ql = Qh + 128 * FP;
    __nv_bfloat16* Kh = Ql + 128 * FP;      // [64][72]
    __nv_bfloat16* Kl = Kh + 64 * FP;
    __nv_bfloat16* Vh = Kl + 64 * FP;
    __nv_bfloat16* Vl = Vh + 64 * FP;

    const int tid = threadIdx.x, lane = tid & 31, wid = tid >> 5;
    const int b = blockIdx.z, h = blockIdx.y, q0 = blockIdx.x * 128;
    const __nv_bfloat16* gq = qs + ((size_t)(b * HH + h) * SS + q0) * 128;
    const __nv_bfloat16* gk = ks + ((size_t)(b * HH + h) * SS) * 128;
    const __nv_bfloat16* gv = vs + ((size_t)(b * HH + h) * SS) * 128;

    #pragma unroll
    for (int t = 0; t < 8; t++) {
        int c = t * 256 + tid;
        int row = c >> 4, sub = c & 15;
        __nv_bfloat16* dst = (sub < 8) ? (Qh + row * FP + sub * 8)
                                       : (Ql + row * FP + (sub - 8) * 8);
        cp16(dst, gq + row * 128 + sub * 8);
    }
    CP_COMMIT();

    auto loadKV = [&](__nv_bfloat16* Ph, __nv_bfloat16* Pl,
                      const __nv_bfloat16* src, int kv0) {
        #pragma unroll
        for (int t = 0; t < 4; t++) {
            int c = t * 256 + tid;
            int row = c >> 4, sub = c & 15;
            __nv_bfloat16* dst = (sub < 8) ? (Ph + row * FP + sub * 8)
                                           : (Pl + row * FP + (sub - 8) * 8);
            cp16(dst, src + (size_t)(kv0 + row) * 128 + sub * 8);
        }
    };
    loadKV(Kh, Kl, gk, 0); CP_COMMIT();
    loadKV(Vh, Vl, gv, 0); CP_COMMIT();

    const int g = lane >> 2, t4 = lane & 3;
    float m0 = -1e30f, m1 = -1e30f, l0 = 0.f, l1 = 0.f;
    float o[8][4];
    #pragma unroll
    for (int j = 0; j < 8; j++)
        #pragma unroll
        for (int r = 0; r < 4; r++) o[j][r] = 0.f;

    const int NT = SS / 64;
    for (int t = 0; t < NT; t++) {
        CP_WAIT(1);
        __syncthreads();

        float s[8][4];
        #pragma unroll
        for (int j = 0; j < 8; j++)
            #pragma unroll
            for (int r = 0; r < 4; r++) s[j][r] = 0.f;

        #pragma unroll
        for (int k16 = 0; k16 < 64; k16 += 16) {
            uint32_t Ah[4], Al[4];
            int arow = wid * 16 + (lane & 15);
            int acol = k16 + (lane >> 4) * 8;
            ldmA4(Ah, Qh + arow * FP + acol);
            ldmA4(Al, Ql + arow * FP + acol);
            #pragma unroll
            for (int nn = 0; nn < 4; nn++) {
                int n0 = nn * 16;
                int brow = n0 + (lane & 7) + ((lane >> 4) ? 8 : 0);
                int bcol = k16 + ((lane >> 3) & 1) * 8;
                uint32_t Bh[4], Bl[4];
                ldmA4(Bh, Kh + brow * FP + bcol);
                mma16816(s[2*nn],   Ah[0], Ah[1], Ah[2], Ah[3], Bh[0], Bh[1]);
                mma16816(s[2*nn+1], Ah[0], Ah[1], Ah[2], Ah[3], Bh[2], Bh[3]);
                mma16816(s[2*nn],   Al[0], Al[1], Al[2], Al[3], Bh[0], Bh[1]);
                mma16816(s[2*nn+1], Al[0], Al[1], Al[2], Al[3], Bh[2], Bh[3]);
                ldmA4(Bl, Kl + brow * FP + bcol);
                mma16816(s[2*nn],   Ah[0], Ah[1], Ah[2], Ah[3], Bl[0], Bl[1]);
                mma16816(s[2*nn+1], Ah[0], Ah[1], Ah[2], Ah[3], Bl[2], Bl[3]);
            }
        }
        __syncthreads();
        if (t + 1 < NT) { loadKV(Kh, Kl, gk, (t + 1) * 64); CP_COMMIT(); CP_WAIT(1); }
        else           { CP_WAIT(0); }

        float mx0 = -1e30f, mx1 = -1e30f;
        #pragma unroll
        for (int j = 0; j < 8; j++) {
            mx0 = fmaxf(mx0, fmaxf(s[j][0], s[j][1]));
            mx1 = fmaxf(mx1, fmaxf(s[j][2], s[j][3]));
        }
        mx0 = fmaxf(mx0, __shfl_xor_sync(0xffffffffu, mx0, 1));
        mx0 = fmaxf(mx0, __shfl_xor_sync(0xffffffffu, mx0, 2));
        mx1 = fmaxf(mx1, __shfl_xor_sync(0xffffffffu, mx1, 1));
        mx1 = fmaxf(mx1, __shfl_xor_sync(0xffffffffu, mx1, 2));
        float mn0 = fmaxf(m0, mx0), mn1 = fmaxf(m1, mx1);
        float a0 = __expf(m0 - mn0), a1 = __expf(m1 - mn1);
        float sum0 = 0.f, sum1 = 0.f;
        #pragma unroll
        for (int j = 0; j < 8; j++) {
            s[j][0] = __expf(s[j][0] - mn0);
            s[j][1] = __expf(s[j][1] - mn0);
            s[j][2] = __expf(s[j][2] - mn1);
            s[j][3] = __expf(s[j][3] - mn1);
            sum0 += s[j][0] + s[j][1];
            sum1 += s[j][2] + s[j][3];
        }
        sum0 += __shfl_xor_sync(0xffffffffu, sum0, 1);
        sum0 += __shfl_xor_sync(0xffffffffu, sum0, 2);
        sum1 += __shfl_xor_sync(0xffffffffu, sum1, 1);
        sum1 += __shfl_xor_sync(0xffffffffu, sum1, 2);
        l0 = l0 * a0 + sum0; l1 = l1 * a1 + sum1;
        m0 = mn0; m1 = mn1;
        #pragma unroll
        for (int j = 0; j < 8; j++) {
            o[j][0] *= a0; o[j][1] *= a0;
            o[j][2] *= a1; o[j][3] *= a1;
        }

        uint32_t aPh[4][4], aPl[4][4];
        #pragma unroll
        for (int j = 0; j < 4; j++) {
            packsplit2(s[2*j][0],   s[2*j][1],   aPh[j][0], aPl[j][0]);
            packsplit2(s[2*j][2],   s[2*j][3],   aPh[j][1], aPl[j][1]);
            packsplit2(s[2*j+1][0], s[2*j+1][1], aPh[j][2], aPl[j][2]);
            packsplit2(s[2*j+1][2], s[2*j+1][3], aPh[j][3], aPl[j][3]);
        }

        __syncthreads();

        #pragma unroll
        for (int j = 0; j < 4; j++) {
            int k0 = j * 16;
            int vrow = k0 + (lane & 7) + (((lane >> 3) & 1) ? 8 : 0);
            #pragma unroll
            for (int nn = 0; nn < 4; nn++) {
                int n0 = nn * 16 + ((lane >> 4) ? 8 : 0);
                uint32_t Bv[4], Bl2[4];
                ldmT4(Bv, Vh + vrow * FP + n0);
                mma16816(o[2*nn],   aPh[j][0], aPh[j][1], aPh[j][2], aPh[j][3], Bv[0], Bv[1]);
                mma16816(o[2*nn+1], aPh[j][0], aPh[j][1], aPh[j][2], aPh[j][3], Bv[2], Bv[3]);
                mma16816(o[2*nn],   aPl[j][0], aPl[j][1], aPl[j][2], aPl[j][3], Bv[0], Bv[1]);
                mma16816(o[2*nn+1], aPl[j][0], aPl[j][1], aPl[j][2], aPl[j][3], Bv[2], Bv[3]);
                ldmT4(Bl2, Vl + vrow * FP + n0);
                mma16816(o[2*nn],   aPh[j][0], aPh[j][1], aPh[j][2], aPh[j][3], Bl2[0], Bl2[1]);
                mma16816(o[2*nn+1], aPh[j][0], aPh[j][1], aPh[j][2], aPh[j][3], Bl2[2], Bl2[3]);
            }
        }
        __syncthreads();
        if (t + 1 < NT) { loadKV(Vh, Vl, gv, (t + 1) * 64); CP_COMMIT(); }
    }

    float inv0 = 1.0f / l0, inv1 = 1.0f / l1;
    int row0 = (b * SS) + q0 + wid * 16 + g;
    int row1 = row0 + 8;
    #pragma unroll
    for (int nt = 0; nt < 8; nt++) {
        int col = h * HD + nt * 8 + t4 * 2;
        uint32_t hp, lp;
        packsplit2(o[nt][0] * inv0, o[nt][1] * inv0, hp, lp);
        uint32_t* d0 = reinterpret_cast<uint32_t*>(ctxs + (size_t)row0 * 2 * DD + col);
        d0[0] = hp; d0[DD / 2] = lp;
        packsplit2(o[nt][2] * inv1, o[nt][3] * inv1, hp, lp);
        uint32_t* d1 = reinterpret_cast<uint32_t*>(ctxs + (size_t)row1 * 2 * DD + col);
        d1[0] = hp; d1[DD / 2] = lp;
    }
}

// ---------------- driver ----------------
#define GEMM_SMEM (3 * GST * 2)                 // 122880 B
#define FLASH_SMEM ((128*FP*2 + 64*FP*4) * 2)   // 73728 B

extern "C" void kernel_launch(void* const* d_in, const int* in_sizes, int n_in,
                              void* d_out, int out_size)
{
    const float* x     = (const float*)d_in[0];
    const float* wq    = (const float*)d_in[1];
    const float* bq    = (const float*)d_in[2];
    const float* wk    = (const float*)d_in[3];
    const float* bk    = (const float*)d_in[4];
    const float* wv    = (const float*)d_in[5];
    const float* bv    = (const float*)d_in[6];
    const float* wo    = (const float*)d_in[7];
    const float* bo    = (const float*)d_in[8];
    const float* w1    = (const float*)d_in[9];
    const float* b1    = (const float*)d_in[10];
    const float* w2    = (const float*)d_in[11];
    const float* b2    = (const float*)d_in[12];
    const float* ln1_g = (const float*)d_in[13];
    const float* ln1_b = (const float*)d_in[14];
    const float* ln2_g = (const float*)d_in[15];
    const float* ln2_b = (const float*)d_in[16];
    const float* lscal = (const float*)d_in[17];
    float* out = (float*)d_out;

    __nv_bfloat16 *xns, *ctxs, *h1s, *wqkvs, *wos, *w1s, *w2s, *qsb, *ksb, *vsb;
    float *qkvf, *x2f, *bqkv;
    cudaGetSymbolAddress((void**)&xns,   g_xns);
    cudaGetSymbolAddress((void**)&ctxs,  g_ctxs);
    cudaGetSymbolAddress((void**)&h1s,   g_h1s);
    cudaGetSymbolAddress((void**)&wqkvs, g_wqkvs);
    cudaGetSymbolAddress((void**)&wos,   g_wos);
    cudaGetSymbolAddress((void**)&w1s,   g_w1s);
    cudaGetSymbolAddress((void**)&w2s,   g_w2s);
    cudaGetSymbolAddress((void**)&qkvf,  g_qkv);
    cudaGetSymbolAddress((void**)&x2f,   g_x2);
    cudaGetSymbolAddress((void**)&qsb,   g_qsb);
    cudaGetSymbolAddress((void**)&ksb,   g_ksb);
    cudaGetSymbolAddress((void**)&vsb,   g_vsb);
    cudaGetSymbolAddress((void**)&bqkv,  g_bqkv);

    cudaFuncSetAttribute(hmma_gemm_kernel<0>, cudaFuncAttributeMaxDynamicSharedMemorySize, GEMM_SMEM);
    cudaFuncSetAttribute(hmma_gemm_kernel<1>, cudaFuncAttributeMaxDynamicSharedMemorySize, GEMM_SMEM);
    cudaFuncSetAttribute(hmma_gemm_kernel<2>, cudaFuncAttributeMaxDynamicSharedMemorySize, GEMM_SMEM);
    cudaFuncSetAttribute(flash_tc_kernel, cudaFuncAttributeMaxDynamicSharedMemorySize, FLASH_SMEM);

    dim3 wb(32, 8);
    // packed QKV weights: rows [0,1024)=wq, [1024,2048)=wk, [2048,3072)=wv
    wsplit_kernel<<<dim3(DD/32,  DD/32),  wb>>>(wq, wqkvs,                        DD, DD);
    wsplit_kernel<<<dim3(DD/32,  DD/32),  wb>>>(wk, wqkvs + (size_t)DD * 2 * DD,  DD, DD);
    wsplit_kernel<<<dim3(DD/32,  DD/32),  wb>>>(wv, wqkvs + (size_t)2*DD * 2 * DD, DD, DD);
    wsplit_kernel<<<dim3(DD/32,  DD/32),  wb>>>(wo, wos, DD,   DD);
    wsplit_kernel<<<dim3(MLPD/32, DD/32), wb>>>(w1, w1s, DD,   MLPD);
    wsplit_kernel<<<dim3(DD/32, MLPD/32), wb>>>(w2, w2s, MLPD, DD);
    packb_kernel<<<12, 256>>>(bq, bk, bv, bqkv);

    ln_split_kernel<<<MM, 256>>>(x, ln1_g, ln1_b, xns);

    dim3 gQKV(3 * DD / 128, MM / 128);   // (24, 32)
    dim3 gD  (DD / 128, MM / 128);       // (8, 32)
    dim3 gMLP1(MLPD / 128, MM / 128);    // (32, 32)

    hmma_gemm_kernel<0><<<gQKV, 256, GEMM_SMEM>>>(xns, wqkvs, bqkv, nullptr, qkvf, nullptr, 3 * DD, DD);

    qkvprep_kernel<<<(MM * HH * 32) / 256, 256>>>(qkvf, lscal, qsb, ksb, vsb);

    flash_tc_kernel<<<dim3(SS / 128, HH, BB), 256, FLASH_SMEM>>>(qsb, ksb, vsb, ctxs);

    hmma_gemm_kernel<1><<<gD, 256, GEMM_SMEM>>>(ctxs, wos, bo, x, x2f, nullptr, DD, DD);

    ln_split_kernel<<<MM, 256>>>(x2f, ln2_g, ln2_b, xns);

    hmma_gemm_kernel<2><<<gMLP1, 256, GEMM_SMEM>>>(xns, w1s, b1, nullptr, nullptr, h1s, MLPD, DD);

    hmma_gemm_kernel<1><<<gD, 256, GEMM_SMEM>>>(h1s, w2s, b2, x2f, out, nullptr, DD, MLPD);
}

// round 6
// speedup vs baseline: 2.6072x; 1.0257x over previous
#include <cuda_runtime.h>
#include <cuda_bf16.h>
#include <math.h>
#include <stdint.h>

// ---------------- problem constants ----------------
#define BB    2
#define SS    2048
#define DD    1024
#define HH    16
#define HD    64
#define MLPD  4096
#define MM    (BB*SS)          // 4096 rows
#define LOG_MAX_F 4.6051702f   // log(1/0.01)

// ---------------- scratch (device globals; no allocs allowed) ----------------
__device__ __align__(16) __nv_bfloat16 g_xns [(size_t)MM * 2 * DD];
__device__ __align__(16) __nv_bfloat16 g_ctxs[(size_t)MM * 2 * DD];
__device__ __align__(16) __nv_bfloat16 g_h1s [(size_t)MM * 2 * MLPD];
__device__ float g_qkv[(size_t)MM * 3 * DD];   // fused QKV output
__device__ float g_x2 [MM*DD];
// per-head split q/k/v for flash: [b,h,s, (hi64|lo64)]
__device__ __align__(16) __nv_bfloat16 g_qsb[(size_t)BB*HH*SS*128];
__device__ __align__(16) __nv_bfloat16 g_ksb[(size_t)BB*HH*SS*128];
__device__ __align__(16) __nv_bfloat16 g_vsb[(size_t)BB*HH*SS*128];
// split+transposed weights: [N, 2K] bf16
__device__ __align__(16) __nv_bfloat16 g_wqkvs[(size_t)(3*DD) * 2 * DD];
__device__ __align__(16) __nv_bfloat16 g_wos  [(size_t)DD * 2 * DD];
__device__ __align__(16) __nv_bfloat16 g_w1s  [(size_t)MLPD * 2 * DD];
__device__ __align__(16) __nv_bfloat16 g_w2s  [(size_t)DD * 2 * MLPD];
__device__ float g_bqkv[3*DD];

__device__ __forceinline__ uint32_t smem_u32(const void* p) {
    return (uint32_t)__cvta_generic_to_shared(p);
}
__device__ __forceinline__ void split2(float v, __nv_bfloat16& hi, __nv_bfloat16& lo) {
    hi = __float2bfloat16(v);
    lo = __float2bfloat16(v - __bfloat162float(hi));
}
__device__ __forceinline__ void cp16(void* dst, const void* src) {
    asm volatile("cp.async.cg.shared.global [%0], [%1], 16;" :: "r"(smem_u32(dst)), "l"(src));
}
#define CP_COMMIT() asm volatile("cp.async.commit_group;" ::: "memory")
#define CP_WAIT(n)  asm volatile("cp.async.wait_group %0;" :: "n"(n) : "memory")

__device__ __forceinline__ void ldmA4(uint32_t* r, const void* p) {
    asm volatile("ldmatrix.sync.aligned.m8n8.x4.shared.b16 {%0,%1,%2,%3}, [%4];"
        : "=r"(r[0]), "=r"(r[1]), "=r"(r[2]), "=r"(r[3]) : "r"(smem_u32(p)));
}
__device__ __forceinline__ void ldmT4(uint32_t* r, const void* p) {
    asm volatile("ldmatrix.sync.aligned.m8n8.x4.trans.shared.b16 {%0,%1,%2,%3}, [%4];"
        : "=r"(r[0]), "=r"(r[1]), "=r"(r[2]), "=r"(r[3]) : "r"(smem_u32(p)));
}
__device__ __forceinline__ void mma16816(float* c, uint32_t a0, uint32_t a1, uint32_t a2,
                                         uint32_t a3, uint32_t b0, uint32_t b1) {
    asm volatile("mma.sync.aligned.m16n8k16.row.col.f32.bf16.bf16.f32 "
        "{%0,%1,%2,%3}, {%4,%5,%6,%7}, {%8,%9}, {%0,%1,%2,%3};"
        : "+f"(c[0]), "+f"(c[1]), "+f"(c[2]), "+f"(c[3])
        : "r"(a0), "r"(a1), "r"(a2), "r"(a3), "r"(b0), "r"(b1));
}
__device__ __forceinline__ void packsplit2(float x, float y, uint32_t& hi, uint32_t& lo) {
    __nv_bfloat16 hx, lx, hy, ly;
    split2(x, hx, lx); split2(y, hy, ly);
    __nv_bfloat162 hp; hp.x = hx; hp.y = hy;
    __nv_bfloat162 lp; lp.x = lx; lp.y = ly;
    hi = *reinterpret_cast<uint32_t*>(&hp);
    lo = *reinterpret_cast<uint32_t*>(&lp);
}

// ---------------- weight transpose + split: W[K,N] f32 -> out[N,2K] bf16 ----
__global__ void __launch_bounds__(256) wsplit_kernel(
    const float* __restrict__ W, __nv_bfloat16* __restrict__ out, int K, int N)
{
    __shared__ float t[32][33];
    int n0 = blockIdx.x * 32, k0 = blockIdx.y * 32;
    int tx = threadIdx.x, ty = threadIdx.y;
    #pragma unroll
    for (int i = ty; i < 32; i += 8)
        t[i][tx] = W[(size_t)(k0 + i) * N + n0 + tx];
    __syncthreads();
    #pragma unroll
    for (int i = ty; i < 32; i += 8) {
        int n = n0 + i, k = k0 + tx;
        float v = t[tx][i];
        __nv_bfloat16 hi, lo; split2(v, hi, lo);
        out[(size_t)n * 2 * K + k]     = hi;
        out[(size_t)n * 2 * K + K + k] = lo;
    }
}

// ---------------- pack qkv bias ----------------------------------------------
__global__ void packb_kernel(const float* __restrict__ bq, const float* __restrict__ bk,
                             const float* __restrict__ bv, float* __restrict__ out)
{
    int i = blockIdx.x * blockDim.x + threadIdx.x;
    if (i < DD)            out[i] = bq[i];
    else if (i < 2 * DD)   out[i] = bk[i - DD];
    else if (i < 3 * DD)   out[i] = bv[i - 2 * DD];
}

// ---------------- LayerNorm -> split bf16 [row, 2D] -------------------------
__global__ void __launch_bounds__(256) ln_split_kernel(
    const float* __restrict__ x, const float* __restrict__ g,
    const float* __restrict__ beta, __nv_bfloat16* __restrict__ outs)
{
    int row = blockIdx.x;
    int tid = threadIdx.x;
    const float4* xr = reinterpret_cast<const float4*>(x + (size_t)row * DD);
    float4 v = xr[tid];
    float s  = v.x + v.y + v.z + v.w;
    float ss = v.x*v.x + v.y*v.y + v.z*v.z + v.w*v.w;
    #pragma unroll
    for (int o = 16; o > 0; o >>= 1) {
        s  += __shfl_xor_sync(0xffffffffu, s,  o);
        ss += __shfl_xor_sync(0xffffffffu, ss, o);
    }
    __shared__ float rs[8], rss[8];
    __shared__ float s_mu, s_rstd;
    int w = tid >> 5;
    if ((tid & 31) == 0) { rs[w] = s; rss[w] = ss; }
    __syncthreads();
    if (tid == 0) {
        float S = 0.f, SSum = 0.f;
        #pragma unroll
        for (int i = 0; i < 8; i++) { S += rs[i]; SSum += rss[i]; }
        float mu  = S * (1.0f / DD);
        float var = SSum * (1.0f / DD) - mu * mu;
        s_mu = mu; s_rstd = rsqrtf(var + 1e-6f);
    }
    __syncthreads();
    float mu = s_mu, rstd = s_rstd;
    float4 gv = reinterpret_cast<const float4*>(g)[tid];
    float4 bv = reinterpret_cast<const float4*>(beta)[tid];
    float o0 = (v.x - mu) * rstd * gv.x + bv.x;
    float o1 = (v.y - mu) * rstd * gv.y + bv.y;
    float o2 = (v.z - mu) * rstd * gv.z + bv.z;
    float o3 = (v.w - mu) * rstd * gv.w + bv.w;
    uint32_t h01, l01, h23, l23;
    packsplit2(o0, o1, h01, l01);
    packsplit2(o2, o3, h23, l23);
    uint32_t* dst = reinterpret_cast<uint32_t*>(outs + (size_t)row * 2 * DD);
    dst[tid * 2]           = h01;
    dst[tid * 2 + 1]       = h23;
    dst[DD/2 + tid * 2]     = l01;
    dst[DD/2 + tid * 2 + 1] = l23;
}

// ---------------- HMMA GEMM: BK=64 chunks, 2-stage pipeline -----------------
// A2: [M, 2K] bf16 (hi|lo), B2: [N, 2K]. acc = Ah*Bh + Al*Bh + Ah*Bl.
// EPI 0: bias -> Cf ; EPI 1: bias+resid -> Cf ; EPI 2: gelu -> split Cs
#define TILE (128 * 72)
#define GST  (4 * TILE)      // halfs per stage: Ahi, Alo, Bhi, Blo
template<int EPI>
__global__ void __launch_bounds__(256) hmma_gemm_kernel(
    const __nv_bfloat16* __restrict__ A2, const __nv_bfloat16* __restrict__ B2,
    const float* __restrict__ bias, const float* __restrict__ resid,
    float* __restrict__ Cf, __nv_bfloat16* __restrict__ Cs, int N, int K)
{
    extern __shared__ __nv_bfloat16 gsm[];

    const int tid  = threadIdx.x;
    const int lane = tid & 31;
    const int wid  = tid >> 5;
    const int wm = wid >> 2, wn = wid & 3;     // 2 x 4 warp grid, warp tile 64x32
    const int rowM0 = blockIdx.y * 128;
    const int colN0 = blockIdx.x * 128;

    const int KC = K >> 6;                     // 64-wide k-chunks
    const size_t strideA = 2 * (size_t)K;

    const int lrow = tid >> 2;
    const int lcol = (tid & 3) * 8;

    float acc[4][4][4];
    #pragma unroll
    for (int a = 0; a < 4; a++)
        #pragma unroll
        for (int b = 0; b < 4; b++)
            #pragma unroll
            for (int r = 0; r < 4; r++) acc[a][b][r] = 0.f;

    auto issue = [&](int c, int buf) {
        int kc = c << 6;
        __nv_bfloat16* Sg = gsm + buf * GST;
        #pragma unroll
        for (int it = 0; it < 2; it++) {
            int row = lrow + it * 64;
            const __nv_bfloat16* Ar = A2 + (size_t)(rowM0 + row) * strideA + kc + lcol;
            const __nv_bfloat16* Br = B2 + (size_t)(colN0 + row) * strideA + kc + lcol;
            #pragma unroll
            for (int hf = 0; hf < 2; hf++) {
                cp16(Sg + 0 * TILE + row * 72 + lcol + hf * 32, Ar + hf * 32);
                cp16(Sg + 1 * TILE + row * 72 + lcol + hf * 32, Ar + K + hf * 32);
                cp16(Sg + 2 * TILE + row * 72 + lcol + hf * 32, Br + hf * 32);
                cp16(Sg + 3 * TILE + row * 72 + lcol + hf * 32, Br + K + hf * 32);
            }
        }
    };

    issue(0, 0); CP_COMMIT();

    for (int c = 0; c < KC; c++) {
        int buf = c & 1;
        if (c + 1 < KC) { issue(c + 1, buf ^ 1); CP_COMMIT(); CP_WAIT(1); }
        else            { CP_WAIT(0); }
        __syncthreads();

        __nv_bfloat16* Sg  = gsm + buf * GST;
        __nv_bfloat16* Ahi = Sg;
        __nv_bfloat16* Alo = Sg + TILE;
        __nv_bfloat16* Bhi = Sg + 2 * TILE;
        __nv_bfloat16* Blo = Sg + 3 * TILE;

        #pragma unroll
        for (int k16 = 0; k16 < 64; k16 += 16) {
            uint32_t Ah[4][4], Al[4][4], Bh[2][4], Bl[2][4];
            const int arow = wm * 64 + (lane & 15);
            const int acol = k16 + (lane >> 4) * 8;
            #pragma unroll
            for (int im = 0; im < 4; im++) {
                ldmA4(Ah[im], Ahi + (arow + im * 16) * 72 + acol);
                ldmA4(Al[im], Alo + (arow + im * 16) * 72 + acol);
            }
            const int brbase = wn * 32 + (lane & 7) + ((lane >> 4) ? 8 : 0);
            const int bcol = k16 + ((lane >> 3) & 1) * 8;
            #pragma unroll
            for (int nb = 0; nb < 2; nb++) {
                ldmA4(Bh[nb], Bhi + (brbase + nb * 16) * 72 + bcol);
                ldmA4(Bl[nb], Blo + (brbase + nb * 16) * 72 + bcol);
            }
            #pragma unroll
            for (int im = 0; im < 4; im++)
                #pragma unroll
                for (int nb = 0; nb < 2; nb++) {
                    float* c0 = acc[im][2 * nb];
                    float* c1 = acc[im][2 * nb + 1];
                    mma16816(c0, Ah[im][0], Ah[im][1], Ah[im][2], Ah[im][3], Bh[nb][0], Bh[nb][1]);
                    mma16816(c1, Ah[im][0], Ah[im][1], Ah[im][2], Ah[im][3], Bh[nb][2], Bh[nb][3]);
                    mma16816(c0, Al[im][0], Al[im][1], Al[im][2], Al[im][3], Bh[nb][0], Bh[nb][1]);
                    mma16816(c1, Al[im][0], Al[im][1], Al[im][2], Al[im][3], Bh[nb][2], Bh[nb][3]);
                    mma16816(c0, Ah[im][0], Ah[im][1], Ah[im][2], Ah[im][3], Bl[nb][0], Bl[nb][1]);
                    mma16816(c1, Ah[im][0], Ah[im][1], Ah[im][2], Ah[im][3], Bl[nb][2], Bl[nb][3]);
                }
        }
        __syncthreads();
    }

    // epilogue: acc[im][j] covers cols wn*32 + (j>>1)*16 + (j&1)*8
    const int g = lane >> 2, t4 = lane & 3;
    #pragma unroll
    for (int im = 0; im < 4; im++) {
        #pragma unroll
        for (int half = 0; half < 2; half++) {
            int row = rowM0 + wm * 64 + im * 16 + g + half * 8;
            #pragma unroll
            for (int j = 0; j < 4; j++) {
                int col = colN0 + wn * 32 + (j >> 1) * 16 + (j & 1) * 8 + t4 * 2;
                float v0 = acc[im][j][half * 2]     + bias[col];
                float v1 = acc[im][j][half * 2 + 1] + bias[col + 1];
                if (EPI == 1) {
                    v0 += resid[(size_t)row * N + col];
                    v1 += resid[(size_t)row * N + col + 1];
                }
                if (EPI == 2) {
                    v0 = 0.5f * v0 * (1.0f + erff(v0 * 0.70710678118f));
                    v1 = 0.5f * v1 * (1.0f + erff(v1 * 0.70710678118f));
                    uint32_t hp, lp;
                    packsplit2(v0, v1, hp, lp);
                    uint32_t* dst = reinterpret_cast<uint32_t*>(Cs + (size_t)row * 2 * N + col);
                    dst[0]     = hp;
                    dst[N / 2] = lp;
                } else {
                    float2 o; o.x = v0; o.y = v1;
                    *reinterpret_cast<float2*>(&Cf[(size_t)row * N + col]) = o;
                }
            }
        }
    }
}

// ---------------- qkv prep: L2-norm q,k (+scale into q), split to [b,h,s,128]
__global__ void __launch_bounds__(256) qkvprep_kernel(
    const float* __restrict__ qkv, const float* __restrict__ logit_scale,
    __nv_bfloat16* __restrict__ qs, __nv_bfloat16* __restrict__ ks,
    __nv_bfloat16* __restrict__ vs)
{
    int gid  = blockIdx.x * blockDim.x + threadIdx.x;
    int wrp  = gid >> 5;
    int lane = gid & 31;
    int token = wrp >> 4;
    int h     = wrp & 15;
    float scale = __expf(fminf(logit_scale[h], LOG_MAX_F));

    const float* base = qkv + (size_t)token * (3 * DD) + h * HD;
    float2 qv = reinterpret_cast<const float2*>(base)[lane];
    float2 kv = reinterpret_cast<const float2*>(base + DD)[lane];
    float2 vv = reinterpret_cast<const float2*>(base + 2 * DD)[lane];
    float sq = qv.x * qv.x + qv.y * qv.y;
    float sk = kv.x * kv.x + kv.y * kv.y;
    #pragma unroll
    for (int o = 16; o > 0; o >>= 1) {
        sq += __shfl_xor_sync(0xffffffffu, sq, o);
        sk += __shfl_xor_sync(0xffffffffu, sk, o);
    }
    float iq = scale / fmaxf(sqrtf(sq), 1e-12f);
    float ik = 1.0f  / fmaxf(sqrtf(sk), 1e-12f);

    int b = token >> 11, s = token & (SS - 1);
    size_t drow = ((size_t)(b * HH + h) * SS + s) * 128;
    uint32_t hi, lo;
    uint32_t* qd = reinterpret_cast<uint32_t*>(qs + drow);
    packsplit2(qv.x * iq, qv.y * iq, hi, lo);
    qd[lane] = hi; qd[32 + lane] = lo;
    uint32_t* kd = reinterpret_cast<uint32_t*>(ks + drow);
    packsplit2(kv.x * ik, kv.y * ik, hi, lo);
    kd[lane] = hi; kd[32 + lane] = lo;
    uint32_t* vd = reinterpret_cast<uint32_t*>(vs + drow);
    packsplit2(vv.x, vv.y, hi, lo);
    vd[lane] = hi; vd[32 + lane] = lo;
}

// ---------------- flash attention, HMMA split-bf16 --------------------------
#define FP 72
__global__ void __launch_bounds__(256) flash_tc_kernel(
    const __nv_bfloat16* __restrict__ qs, const __nv_bfloat16* __restrict__ ks,
    const __nv_bfloat16* __restrict__ vs, __nv_bfloat16* __restrict__ ctxs)
{
    extern __shared__ __nv_bfloat16 fsm[];
    __nv_bfloat16* Qh = fsm;                // [128][72]
    __nv_bfloat16* Ql = Qh + 128 * FP;
    __nv_bfloat16* Kh = Ql + 128 * FP;      // [64][72]
    __nv_bfloat16* Kl = Kh + 64 * FP;
    __nv_bfloat16* Vh = Kl + 64 * FP;
    __nv_bfloat16* Vl = Vh + 64 * FP;

    const int tid = threadIdx.x, lane = tid & 31, wid = tid >> 5;
    const int b = blockIdx.z, h = blockIdx.y, q0 = blockIdx.x * 128;
    const __nv_bfloat16* gq = qs + ((size_t)(b * HH + h) * SS + q0) * 128;
    const __nv_bfloat16* gk = ks + ((size_t)(b * HH + h) * SS) * 128;
    const __nv_bfloat16* gv = vs + ((size_t)(b * HH + h) * SS) * 128;

    #pragma unroll
    for (int t = 0; t < 8; t++) {
        int c = t * 256 + tid;
        int row = c >> 4, sub = c & 15;
        __nv_bfloat16* dst = (sub < 8) ? (Qh + row * FP + sub * 8)
                                       : (Ql + row * FP + (sub - 8) * 8);
        cp16(dst, gq + row * 128 + sub * 8);
    }
    CP_COMMIT();

    auto loadKV = [&](__nv_bfloat16* Ph, __nv_bfloat16* Pl,
                      const __nv_bfloat16* src, int kv0) {
        #pragma unroll
        for (int t = 0; t < 4; t++) {
            int c = t * 256 + tid;
            int row = c >> 4, sub = c & 15;
            __nv_bfloat16* dst = (sub < 8) ? (Ph + row * FP + sub * 8)
                                           : (Pl + row * FP + (sub - 8) * 8);
            cp16(dst, src + (size_t)(kv0 + row) * 128 + sub * 8);
        }
    };
    loadKV(Kh, Kl, gk, 0); CP_COMMIT();
    loadKV(Vh, Vl, gv, 0); CP_COMMIT();

    const int g = lane >> 2, t4 = lane & 3;
    float m0 = -1e30f, m1 = -1e30f, l0 = 0.f, l1 = 0.f;
    float o[8][4];
    #pragma unroll
    for (int j = 0; j < 8; j++)
        #pragma unroll
        for (int r = 0; r < 4; r++) o[j][r] = 0.f;

    const int NT = SS / 64;
    for (int t = 0; t < NT; t++) {
        CP_WAIT(1);
        __syncthreads();

        float s[8][4];
        #pragma unroll
        for (int j = 0; j < 8; j++)
            #pragma unroll
            for (int r = 0; r < 4; r++) s[j][r] = 0.f;

        #pragma unroll
        for (int k16 = 0; k16 < 64; k16 += 16) {
            uint32_t Ah[4], Al[4];
            int arow = wid * 16 + (lane & 15);
            int acol = k16 + (lane >> 4) * 8;
            ldmA4(Ah, Qh + arow * FP + acol);
            ldmA4(Al, Ql + arow * FP + acol);
            #pragma unroll
            for (int nn = 0; nn < 4; nn++) {
                int n0 = nn * 16;
                int brow = n0 + (lane & 7) + ((lane >> 4) ? 8 : 0);
                int bcol = k16 + ((lane >> 3) & 1) * 8;
                uint32_t Bh[4], Bl[4];
                ldmA4(Bh, Kh + brow * FP + bcol);
                mma16816(s[2*nn],   Ah[0], Ah[1], Ah[2], Ah[3], Bh[0], Bh[1]);
                mma16816(s[2*nn+1], Ah[0], Ah[1], Ah[2], Ah[3], Bh[2], Bh[3]);
                mma16816(s[2*nn],   Al[0], Al[1], Al[2], Al[3], Bh[0], Bh[1]);
                mma16816(s[2*nn+1], Al[0], Al[1], Al[2], Al[3], Bh[2], Bh[3]);
                ldmA4(Bl, Kl + brow * FP + bcol);
                mma16816(s[2*nn],   Ah[0], Ah[1], Ah[2], Ah[3], Bl[0], Bl[1]);
                mma16816(s[2*nn+1], Ah[0], Ah[1], Ah[2], Ah[3], Bl[2], Bl[3]);
            }
        }
        __syncthreads();
        if (t + 1 < NT) { loadKV(Kh, Kl, gk, (t + 1) * 64); CP_COMMIT(); CP_WAIT(1); }
        else           { CP_WAIT(0); }

        float mx0 = -1e30f, mx1 = -1e30f;
        #pragma unroll
        for (int j = 0; j < 8; j++) {
            mx0 = fmaxf(mx0, fmaxf(s[j][0], s[j][1]));
            mx1 = fmaxf(mx1, fmaxf(s[j][2], s[j][3]));
        }
        mx0 = fmaxf(mx0, __shfl_xor_sync(0xffffffffu, mx0, 1));
        mx0 = fmaxf(mx0, __shfl_xor_sync(0xffffffffu, mx0, 2));
        mx1 = fmaxf(mx1, __shfl_xor_sync(0xffffffffu, mx1, 1));
        mx1 = fmaxf(mx1, __shfl_xor_sync(0xffffffffu, mx1, 2));
        float mn0 = fmaxf(m0, mx0), mn1 = fmaxf(m1, mx1);
        float a0 = __expf(m0 - mn0), a1 = __expf(m1 - mn1);
        float sum0 = 0.f, sum1 = 0.f;
        #pragma unroll
        for (int j = 0; j < 8; j++) {
            s[j][0] = __expf(s[j][0] - mn0);
            s[j][1] = __expf(s[j][1] - mn0);
            s[j][2] = __expf(s[j][2] - mn1);
            s[j][3] = __expf(s[j][3] - mn1);
            sum0 += s[j][0] + s[j][1];
            sum1 += s[j][2] + s[j][3];
        }
        sum0 += __shfl_xor_sync(0xffffffffu, sum0, 1);
        sum0 += __shfl_xor_sync(0xffffffffu, sum0, 2);
        sum1 += __shfl_xor_sync(0xffffffffu, sum1, 1);
        sum1 += __shfl_xor_sync(0xffffffffu, sum1, 2);
        l0 = l0 * a0 + sum0; l1 = l1 * a1 + sum1;
        m0 = mn0; m1 = mn1;
        #pragma unroll
        for (int j = 0; j < 8; j++) {
            o[j][0] *= a0; o[j][1] *= a0;
            o[j][2] *= a1; o[j][3] *= a1;
        }

        uint32_t aPh[4][4], aPl[4][4];
        #pragma unroll
        for (int j = 0; j < 4; j++) {
            packsplit2(s[2*j][0],   s[2*j][1],   aPh[j][0], aPl[j][0]);
            packsplit2(s[2*j][2],   s[2*j][3],   aPh[j][1], aPl[j][1]);
            packsplit2(s[2*j+1][0], s[2*j+1][1], aPh[j][2], aPl[j][2]);
            packsplit2(s[2*j+1][2], s[2*j+1][3], aPh[j][3], aPl[j][3]);
        }

        __syncthreads();

        #pragma unroll
        for (int j = 0; j < 4; j++) {
            int k0 = j * 16;
            int vrow = k0 + (lane & 7) + (((lane >> 3) & 1) ? 8 : 0);
            #pragma unroll
            for (int nn = 0; nn < 4; nn++) {
                int n0 = nn * 16 + ((lane >> 4) ? 8 : 0);
                uint32_t Bv[4], Bl2[4];
                ldmT4(Bv, Vh + vrow * FP + n0);
                mma16816(o[2*nn],   aPh[j][0], aPh[j][1], aPh[j][2], aPh[j][3], Bv[0], Bv[1]);
                mma16816(o[2*nn+1], aPh[j][0], aPh[j][1], aPh[j][2], aPh[j][3], Bv[2], Bv[3]);
                mma16816(o[2*nn],   aPl[j][0], aPl[j][1], aPl[j][2], aPl[j][3], Bv[0], Bv[1]);
                mma16816(o[2*nn+1], aPl[j][0], aPl[j][1], aPl[j][2], aPl[j][3], Bv[2], Bv[3]);
                ldmT4(Bl2, Vl + vrow * FP + n0);
                mma16816(o[2*nn],   aPh[j][0], aPh[j][1], aPh[j][2], aPh[j][3], Bl2[0], Bl2[1]);
                mma16816(o[2*nn+1], aPh[j][0], aPh[j][1], aPh[j][2], aPh[j][3], Bl2[2], Bl2[3]);
            }
        }
        __syncthreads();
        if (t + 1 < NT) { loadKV(Vh, Vl, gv, (t + 1) * 64); CP_COMMIT(); }
    }

    float inv0 = 1.0f / l0, inv1 = 1.0f / l1;
    int row0 = (b * SS) + q0 + wid * 16 + g;
    int row1 = row0 + 8;
    #pragma unroll
    for (int nt = 0; nt < 8; nt++) {
        int col = h * HD + nt * 8 + t4 * 2;
        uint32_t hp, lp;
        packsplit2(o[nt][0] * inv0, o[nt][1] * inv0, hp, lp);
        uint32_t* d0 = reinterpret_cast<uint32_t*>(ctxs + (size_t)row0 * 2 * DD + col);
        d0[0] = hp; d0[DD / 2] = lp;
        packsplit2(o[nt][2] * inv1, o[nt][3] * inv1, hp, lp);
        uint32_t* d1 = reinterpret_cast<uint32_t*>(ctxs + (size_t)row1 * 2 * DD + col);
        d1[0] = hp; d1[DD / 2] = lp;
    }
}

// ---------------- driver ----------------
#define GEMM_SMEM (2 * GST * 2)                 // 147456 B
#define FLASH_SMEM ((128*FP*2 + 64*FP*4) * 2)   // 73728 B

extern "C" void kernel_launch(void* const* d_in, const int* in_sizes, int n_in,
                              void* d_out, int out_size)
{
    const float* x     = (const float*)d_in[0];
    const float* wq    = (const float*)d_in[1];
    const float* bq    = (const float*)d_in[2];
    const float* wk    = (const float*)d_in[3];
    const float* bk    = (const float*)d_in[4];
    const float* wv    = (const float*)d_in[5];
    const float* bv    = (const float*)d_in[6];
    const float* wo    = (const float*)d_in[7];
    const float* bo    = (const float*)d_in[8];
    const float* w1    = (const float*)d_in[9];
    const float* b1    = (const float*)d_in[10];
    const float* w2    = (const float*)d_in[11];
    const float* b2    = (const float*)d_in[12];
    const float* ln1_g = (const float*)d_in[13];
    const float* ln1_b = (const float*)d_in[14];
    const float* ln2_g = (const float*)d_in[15];
    const float* ln2_b = (const float*)d_in[16];
    const float* lscal = (const float*)d_in[17];
    float* out = (float*)d_out;

    __nv_bfloat16 *xns, *ctxs, *h1s, *wqkvs, *wos, *w1s, *w2s, *qsb, *ksb, *vsb;
    float *qkvf, *x2f, *bqkv;
    cudaGetSymbolAddress((void**)&xns,   g_xns);
    cudaGetSymbolAddress((void**)&ctxs,  g_ctxs);
    cudaGetSymbolAddress((void**)&h1s,   g_h1s);
    cudaGetSymbolAddress((void**)&wqkvs, g_wqkvs);
    cudaGetSymbolAddress((void**)&wos,   g_wos);
    cudaGetSymbolAddress((void**)&w1s,   g_w1s);
    cudaGetSymbolAddress((void**)&w2s,   g_w2s);
    cudaGetSymbolAddress((void**)&qkvf,  g_qkv);
    cudaGetSymbolAddress((void**)&x2f,   g_x2);
    cudaGetSymbolAddress((void**)&qsb,   g_qsb);
    cudaGetSymbolAddress((void**)&ksb,   g_ksb);
    cudaGetSymbolAddress((void**)&vsb,   g_vsb);
    cudaGetSymbolAddress((void**)&bqkv,  g_bqkv);

    cudaFuncSetAttribute(hmma_gemm_kernel<0>, cudaFuncAttributeMaxDynamicSharedMemorySize, GEMM_SMEM);
    cudaFuncSetAttribute(hmma_gemm_kernel<1>, cudaFuncAttributeMaxDynamicSharedMemorySize, GEMM_SMEM);
    cudaFuncSetAttribute(hmma_gemm_kernel<2>, cudaFuncAttributeMaxDynamicSharedMemorySize, GEMM_SMEM);
    cudaFuncSetAttribute(flash_tc_kernel, cudaFuncAttributeMaxDynamicSharedMemorySize, FLASH_SMEM);

    dim3 wb(32, 8);
    // launches 1-5: wq/wk/wv splits, packb, ln1  (ncu -s 5 -c 1 captures launch #6 = QKV GEMM)
    wsplit_kernel<<<dim3(DD/32,  DD/32),  wb>>>(wq, wqkvs,                         DD, DD);
    wsplit_kernel<<<dim3(DD/32,  DD/32),  wb>>>(wk, wqkvs + (size_t)DD * 2 * DD,   DD, DD);
    wsplit_kernel<<<dim3(DD/32,  DD/32),  wb>>>(wv, wqkvs + (size_t)2*DD * 2 * DD, DD, DD);
    packb_kernel<<<12, 256>>>(bq, bk, bv, bqkv);
    ln_split_kernel<<<MM, 256>>>(x, ln1_g, ln1_b, xns);

    dim3 gQKV(3 * DD / 128, MM / 128);   // (24, 32)
    dim3 gD  (DD / 128, MM / 128);       // (8, 32)
    dim3 gMLP1(MLPD / 128, MM / 128);    // (32, 32)

    // launch #6: the hot QKV GEMM
    hmma_gemm_kernel<0><<<gQKV, 256, GEMM_SMEM>>>(xns, wqkvs, bqkv, nullptr, qkvf, nullptr, 3 * DD, DD);

    // remaining weight splits (stream-ordered; complete before their GEMMs)
    wsplit_kernel<<<dim3(DD/32,  DD/32),  wb>>>(wo, wos, DD,   DD);
    wsplit_kernel<<<dim3(MLPD/32, DD/32), wb>>>(w1, w1s, DD,   MLPD);
    wsplit_kernel<<<dim3(DD/32, MLPD/32), wb>>>(w2, w2s, MLPD, DD);

    qkvprep_kernel<<<(MM * HH * 32) / 256, 256>>>(qkvf, lscal, qsb, ksb, vsb);

    flash_tc_kernel<<<dim3(SS / 128, HH, BB), 256, FLASH_SMEM>>>(qsb, ksb, vsb, ctxs);

    hmma_gemm_kernel<1><<<gD, 256, GEMM_SMEM>>>(ctxs, wos, bo, x, x2f, nullptr, DD, DD);

    ln_split_kernel<<<MM, 256>>>(x2f, ln2_g, ln2_b, xns);

    hmma_gemm_kernel<2><<<gMLP1, 256, GEMM_SMEM>>>(xns, w1s, b1, nullptr, nullptr, h1s, MLPD, DD);

    hmma_gemm_kernel<1><<<gD, 256, GEMM_SMEM>>>(h1s, w2s, b2, x2f, out, nullptr, DD, MLPD);
}

// round 7
// speedup vs baseline: 2.7580x; 1.0578x over previous
#include <cuda_runtime.h>
#include <cuda_bf16.h>
#include <math.h>
#include <stdint.h>

// ---------------- problem constants ----------------
#define BB    2
#define SS    2048
#define DD    1024
#define HH    16
#define HD    64
#define MLPD  4096
#define MM    (BB*SS)          // 4096 rows
#define LOG_MAX_F 4.6051702f   // log(1/0.01)

// ---------------- scratch (device globals; no allocs allowed) ----------------
__device__ __align__(16) __nv_bfloat16 g_xns [(size_t)MM * 2 * DD];
__device__ __align__(16) __nv_bfloat16 g_ctxs[(size_t)MM * 2 * DD];
__device__ __align__(16) __nv_bfloat16 g_h1s [(size_t)MM * 2 * MLPD];
__device__ float g_qkv[(size_t)MM * 3 * DD];   // fused QKV output
__device__ float g_x2 [MM*DD];
// per-head split q/k/v for flash: [b,h,s, (hi64|lo64)]
__device__ __align__(16) __nv_bfloat16 g_qsb[(size_t)BB*HH*SS*128];
__device__ __align__(16) __nv_bfloat16 g_ksb[(size_t)BB*HH*SS*128];
__device__ __align__(16) __nv_bfloat16 g_vsb[(size_t)BB*HH*SS*128];
// split+transposed weights: [N, 2K] bf16
__device__ __align__(16) __nv_bfloat16 g_wqkvs[(size_t)(3*DD) * 2 * DD];
__device__ __align__(16) __nv_bfloat16 g_wos  [(size_t)DD * 2 * DD];
__device__ __align__(16) __nv_bfloat16 g_w1s  [(size_t)MLPD * 2 * DD];
__device__ __align__(16) __nv_bfloat16 g_w2s  [(size_t)DD * 2 * MLPD];
__device__ float g_bqkv[3*DD];

__device__ __forceinline__ uint32_t smem_u32(const void* p) {
    return (uint32_t)__cvta_generic_to_shared(p);
}
__device__ __forceinline__ void split2(float v, __nv_bfloat16& hi, __nv_bfloat16& lo) {
    hi = __float2bfloat16(v);
    lo = __float2bfloat16(v - __bfloat162float(hi));
}
__device__ __forceinline__ void cp16(void* dst, const void* src) {
    asm volatile("cp.async.cg.shared.global [%0], [%1], 16;" :: "r"(smem_u32(dst)), "l"(src));
}
#define CP_COMMIT() asm volatile("cp.async.commit_group;" ::: "memory")
#define CP_WAIT(n)  asm volatile("cp.async.wait_group %0;" :: "n"(n) : "memory")

__device__ __forceinline__ void ldmA4(uint32_t* r, const void* p) {
    asm volatile("ldmatrix.sync.aligned.m8n8.x4.shared.b16 {%0,%1,%2,%3}, [%4];"
        : "=r"(r[0]), "=r"(r[1]), "=r"(r[2]), "=r"(r[3]) : "r"(smem_u32(p)));
}
__device__ __forceinline__ void ldmT4(uint32_t* r, const void* p) {
    asm volatile("ldmatrix.sync.aligned.m8n8.x4.trans.shared.b16 {%0,%1,%2,%3}, [%4];"
        : "=r"(r[0]), "=r"(r[1]), "=r"(r[2]), "=r"(r[3]) : "r"(smem_u32(p)));
}
__device__ __forceinline__ void mma16816(float* c, uint32_t a0, uint32_t a1, uint32_t a2,
                                         uint32_t a3, uint32_t b0, uint32_t b1) {
    asm volatile("mma.sync.aligned.m16n8k16.row.col.f32.bf16.bf16.f32 "
        "{%0,%1,%2,%3}, {%4,%5,%6,%7}, {%8,%9}, {%0,%1,%2,%3};"
        : "+f"(c[0]), "+f"(c[1]), "+f"(c[2]), "+f"(c[3])
        : "r"(a0), "r"(a1), "r"(a2), "r"(a3), "r"(b0), "r"(b1));
}
__device__ __forceinline__ void packsplit2(float x, float y, uint32_t& hi, uint32_t& lo) {
    __nv_bfloat16 hx, lx, hy, ly;
    split2(x, hx, lx); split2(y, hy, ly);
    __nv_bfloat162 hp; hp.x = hx; hp.y = hy;
    __nv_bfloat162 lp; lp.x = lx; lp.y = ly;
    hi = *reinterpret_cast<uint32_t*>(&hp);
    lo = *reinterpret_cast<uint32_t*>(&lp);
}

// ---------------- weight transpose + split: W[K,N] f32 -> out[N,2K] bf16 ----
__global__ void __launch_bounds__(256) wsplit_kernel(
    const float* __restrict__ W, __nv_bfloat16* __restrict__ out, int K, int N)
{
    __shared__ float t[32][33];
    int n0 = blockIdx.x * 32, k0 = blockIdx.y * 32;
    int tx = threadIdx.x, ty = threadIdx.y;
    #pragma unroll
    for (int i = ty; i < 32; i += 8)
        t[i][tx] = W[(size_t)(k0 + i) * N + n0 + tx];
    __syncthreads();
    #pragma unroll
    for (int i = ty; i < 32; i += 8) {
        int n = n0 + i, k = k0 + tx;
        float v = t[tx][i];
        __nv_bfloat16 hi, lo; split2(v, hi, lo);
        out[(size_t)n * 2 * K + k]     = hi;
        out[(size_t)n * 2 * K + K + k] = lo;
    }
}

// fused wq/wk/wv split (z selects weight) so the QKV GEMM is launch #4
__global__ void __launch_bounds__(256) wsplit3_kernel(
    const float* __restrict__ W0, const float* __restrict__ W1,
    const float* __restrict__ W2, __nv_bfloat16* __restrict__ out)
{
    __shared__ float t[32][33];
    const float* W = (blockIdx.z == 0) ? W0 : (blockIdx.z == 1) ? W1 : W2;
    __nv_bfloat16* o = out + (size_t)blockIdx.z * DD * 2 * DD;
    int n0 = blockIdx.x * 32, k0 = blockIdx.y * 32;
    int tx = threadIdx.x, ty = threadIdx.y;
    #pragma unroll
    for (int i = ty; i < 32; i += 8)
        t[i][tx] = W[(size_t)(k0 + i) * DD + n0 + tx];
    __syncthreads();
    #pragma unroll
    for (int i = ty; i < 32; i += 8) {
        int n = n0 + i, k = k0 + tx;
        float v = t[tx][i];
        __nv_bfloat16 hi, lo; split2(v, hi, lo);
        o[(size_t)n * 2 * DD + k]      = hi;
        o[(size_t)n * 2 * DD + DD + k] = lo;
    }
}

// ---------------- pack qkv bias ----------------------------------------------
__global__ void packb_kernel(const float* __restrict__ bq, const float* __restrict__ bk,
                             const float* __restrict__ bv, float* __restrict__ out)
{
    int i = blockIdx.x * blockDim.x + threadIdx.x;
    if (i < DD)            out[i] = bq[i];
    else if (i < 2 * DD)   out[i] = bk[i - DD];
    else if (i < 3 * DD)   out[i] = bv[i - 2 * DD];
}

// ---------------- LayerNorm -> split bf16 [row, 2D] -------------------------
__global__ void __launch_bounds__(256) ln_split_kernel(
    const float* __restrict__ x, const float* __restrict__ g,
    const float* __restrict__ beta, __nv_bfloat16* __restrict__ outs)
{
    int row = blockIdx.x;
    int tid = threadIdx.x;
    const float4* xr = reinterpret_cast<const float4*>(x + (size_t)row * DD);
    float4 v = xr[tid];
    float s  = v.x + v.y + v.z + v.w;
    float ss = v.x*v.x + v.y*v.y + v.z*v.z + v.w*v.w;
    #pragma unroll
    for (int o = 16; o > 0; o >>= 1) {
        s  += __shfl_xor_sync(0xffffffffu, s,  o);
        ss += __shfl_xor_sync(0xffffffffu, ss, o);
    }
    __shared__ float rs[8], rss[8];
    __shared__ float s_mu, s_rstd;
    int w = tid >> 5;
    if ((tid & 31) == 0) { rs[w] = s; rss[w] = ss; }
    __syncthreads();
    if (tid == 0) {
        float S = 0.f, SSum = 0.f;
        #pragma unroll
        for (int i = 0; i < 8; i++) { S += rs[i]; SSum += rss[i]; }
        float mu  = S * (1.0f / DD);
        float var = SSum * (1.0f / DD) - mu * mu;
        s_mu = mu; s_rstd = rsqrtf(var + 1e-6f);
    }
    __syncthreads();
    float mu = s_mu, rstd = s_rstd;
    float4 gv = reinterpret_cast<const float4*>(g)[tid];
    float4 bv = reinterpret_cast<const float4*>(beta)[tid];
    float o0 = (v.x - mu) * rstd * gv.x + bv.x;
    float o1 = (v.y - mu) * rstd * gv.y + bv.y;
    float o2 = (v.z - mu) * rstd * gv.z + bv.z;
    float o3 = (v.w - mu) * rstd * gv.w + bv.w;
    uint32_t h01, l01, h23, l23;
    packsplit2(o0, o1, h01, l01);
    packsplit2(o2, o3, h23, l23);
    uint32_t* dst = reinterpret_cast<uint32_t*>(outs + (size_t)row * 2 * DD);
    dst[tid * 2]           = h01;
    dst[tid * 2 + 1]       = h23;
    dst[DD/2 + tid * 2]     = l01;
    dst[DD/2 + tid * 2 + 1] = l23;
}

// ---------------- HMMA GEMM: 512 threads, 4x4 warp grid, 32x32 warp tiles ---
// A2: [M, 2K] bf16 (hi|lo), B2: [N, 2K]. acc = Ah*Bh + Al*Bh + Ah*Bl.
// EPI 0: bias -> Cf ; EPI 1: bias+resid -> Cf ; EPI 2: gelu -> split Cs
#define TILE (128 * 72)
#define GST  (4 * TILE)      // halfs per stage: Ahi, Alo, Bhi, Blo
template<int EPI>
__global__ void __launch_bounds__(512) hmma_gemm_kernel(
    const __nv_bfloat16* __restrict__ A2, const __nv_bfloat16* __restrict__ B2,
    const float* __restrict__ bias, const float* __restrict__ resid,
    float* __restrict__ Cf, __nv_bfloat16* __restrict__ Cs, int N, int K)
{
    extern __shared__ __nv_bfloat16 gsm[];

    const int tid  = threadIdx.x;
    const int lane = tid & 31;
    const int wid  = tid >> 5;
    const int wm = wid >> 2, wn = wid & 3;     // 4 x 4 warp grid, warp tile 32x32
    const int rowM0 = blockIdx.y * 128;
    const int colN0 = blockIdx.x * 128;

    const int KC = K >> 6;                     // 64-wide k-chunks
    const size_t strideA = 2 * (size_t)K;

    const int lrow = tid >> 3;          // 0..63
    const int lcol = (tid & 7) * 8;     // 0..56

    float acc[2][4][4];
    #pragma unroll
    for (int a = 0; a < 2; a++)
        #pragma unroll
        for (int b = 0; b < 4; b++)
            #pragma unroll
            for (int r = 0; r < 4; r++) acc[a][b][r] = 0.f;

    auto issue = [&](int c, int buf) {
        int kc = c << 6;
        __nv_bfloat16* Sg = gsm + buf * GST;
        #pragma unroll
        for (int it = 0; it < 2; it++) {
            int row = lrow + it * 64;
            const __nv_bfloat16* Ar = A2 + (size_t)(rowM0 + row) * strideA + kc + lcol;
            const __nv_bfloat16* Br = B2 + (size_t)(colN0 + row) * strideA + kc + lcol;
            cp16(Sg + 0 * TILE + row * 72 + lcol, Ar);
            cp16(Sg + 1 * TILE + row * 72 + lcol, Ar + K);
            cp16(Sg + 2 * TILE + row * 72 + lcol, Br);
            cp16(Sg + 3 * TILE + row * 72 + lcol, Br + K);
        }
    };

    issue(0, 0); CP_COMMIT();

    for (int c = 0; c < KC; c++) {
        int buf = c & 1;
        if (c + 1 < KC) { issue(c + 1, buf ^ 1); CP_COMMIT(); CP_WAIT(1); }
        else            { CP_WAIT(0); }
        __syncthreads();

        __nv_bfloat16* Sg  = gsm + buf * GST;
        __nv_bfloat16* Ahi = Sg;
        __nv_bfloat16* Alo = Sg + TILE;
        __nv_bfloat16* Bhi = Sg + 2 * TILE;
        __nv_bfloat16* Blo = Sg + 3 * TILE;

        #pragma unroll
        for (int k16 = 0; k16 < 64; k16 += 16) {
            uint32_t Ah[2][4], Al[2][4], Bh[2][4], Bl[2][4];
            const int arow = wm * 32 + (lane & 15);
            const int acol = k16 + (lane >> 4) * 8;
            #pragma unroll
            for (int im = 0; im < 2; im++) {
                ldmA4(Ah[im], Ahi + (arow + im * 16) * 72 + acol);
                ldmA4(Al[im], Alo + (arow + im * 16) * 72 + acol);
            }
            const int brbase = wn * 32 + (lane & 7) + ((lane >> 4) ? 8 : 0);
            const int bcol = k16 + ((lane >> 3) & 1) * 8;
            #pragma unroll
            for (int nb = 0; nb < 2; nb++) {
                ldmA4(Bh[nb], Bhi + (brbase + nb * 16) * 72 + bcol);
                ldmA4(Bl[nb], Blo + (brbase + nb * 16) * 72 + bcol);
            }
            #pragma unroll
            for (int im = 0; im < 2; im++)
                #pragma unroll
                for (int nb = 0; nb < 2; nb++) {
                    float* c0 = acc[im][2 * nb];
                    float* c1 = acc[im][2 * nb + 1];
                    mma16816(c0, Ah[im][0], Ah[im][1], Ah[im][2], Ah[im][3], Bh[nb][0], Bh[nb][1]);
                    mma16816(c1, Ah[im][0], Ah[im][1], Ah[im][2], Ah[im][3], Bh[nb][2], Bh[nb][3]);
                    mma16816(c0, Al[im][0], Al[im][1], Al[im][2], Al[im][3], Bh[nb][0], Bh[nb][1]);
                    mma16816(c1, Al[im][0], Al[im][1], Al[im][2], Al[im][3], Bh[nb][2], Bh[nb][3]);
                    mma16816(c0, Ah[im][0], Ah[im][1], Ah[im][2], Ah[im][3], Bl[nb][0], Bl[nb][1]);
                    mma16816(c1, Ah[im][0], Ah[im][1], Ah[im][2], Ah[im][3], Bl[nb][2], Bl[nb][3]);
                }
        }
        __syncthreads();
    }

    // epilogue: acc[im][j] covers cols wn*32 + (j>>1)*16 + (j&1)*8
    const int g = lane >> 2, t4 = lane & 3;
    #pragma unroll
    for (int im = 0; im < 2; im++) {
        #pragma unroll
        for (int half = 0; half < 2; half++) {
            int row = rowM0 + wm * 32 + im * 16 + g + half * 8;
            #pragma unroll
            for (int j = 0; j < 4; j++) {
                int col = colN0 + wn * 32 + (j >> 1) * 16 + (j & 1) * 8 + t4 * 2;
                float v0 = acc[im][j][half * 2]     + bias[col];
                float v1 = acc[im][j][half * 2 + 1] + bias[col + 1];
                if (EPI == 1) {
                    v0 += resid[(size_t)row * N + col];
                    v1 += resid[(size_t)row * N + col + 1];
                }
                if (EPI == 2) {
                    v0 = 0.5f * v0 * (1.0f + erff(v0 * 0.70710678118f));
                    v1 = 0.5f * v1 * (1.0f + erff(v1 * 0.70710678118f));
                    uint32_t hp, lp;
                    packsplit2(v0, v1, hp, lp);
                    uint32_t* dst = reinterpret_cast<uint32_t*>(Cs + (size_t)row * 2 * N + col);
                    dst[0]     = hp;
                    dst[N / 2] = lp;
                } else {
                    float2 o; o.x = v0; o.y = v1;
                    *reinterpret_cast<float2*>(&Cf[(size_t)row * N + col]) = o;
                }
            }
        }
    }
}

// ---------------- qkv prep: L2-norm q,k (+scale into q), split to [b,h,s,128]
__global__ void __launch_bounds__(256) qkvprep_kernel(
    const float* __restrict__ qkv, const float* __restrict__ logit_scale,
    __nv_bfloat16* __restrict__ qs, __nv_bfloat16* __restrict__ ks,
    __nv_bfloat16* __restrict__ vs)
{
    int gid  = blockIdx.x * blockDim.x + threadIdx.x;
    int wrp  = gid >> 5;
    int lane = gid & 31;
    int token = wrp >> 4;
    int h     = wrp & 15;
    float scale = __expf(fminf(logit_scale[h], LOG_MAX_F));

    const float* base = qkv + (size_t)token * (3 * DD) + h * HD;
    float2 qv = reinterpret_cast<const float2*>(base)[lane];
    float2 kv = reinterpret_cast<const float2*>(base + DD)[lane];
    float2 vv = reinterpret_cast<const float2*>(base + 2 * DD)[lane];
    float sq = qv.x * qv.x + qv.y * qv.y;
    float sk = kv.x * kv.x + kv.y * kv.y;
    #pragma unroll
    for (int o = 16; o > 0; o >>= 1) {
        sq += __shfl_xor_sync(0xffffffffu, sq, o);
        sk += __shfl_xor_sync(0xffffffffu, sk, o);
    }
    float iq = scale / fmaxf(sqrtf(sq), 1e-12f);
    float ik = 1.0f  / fmaxf(sqrtf(sk), 1e-12f);

    int b = token >> 11, s = token & (SS - 1);
    size_t drow = ((size_t)(b * HH + h) * SS + s) * 128;
    uint32_t hi, lo;
    uint32_t* qd = reinterpret_cast<uint32_t*>(qs + drow);
    packsplit2(qv.x * iq, qv.y * iq, hi, lo);
    qd[lane] = hi; qd[32 + lane] = lo;
    uint32_t* kd = reinterpret_cast<uint32_t*>(ks + drow);
    packsplit2(kv.x * ik, kv.y * ik, hi, lo);
    kd[lane] = hi; kd[32 + lane] = lo;
    uint32_t* vd = reinterpret_cast<uint32_t*>(vs + drow);
    packsplit2(vv.x, vv.y, hi, lo);
    vd[lane] = hi; vd[32 + lane] = lo;
}

// ---------------- flash attention, HMMA split-bf16 --------------------------
#define FP 72
__global__ void __launch_bounds__(256) flash_tc_kernel(
    const __nv_bfloat16* __restrict__ qs, const __nv_bfloat16* __restrict__ ks,
    const __nv_bfloat16* __restrict__ vs, __nv_bfloat16* __restrict__ ctxs)
{
    extern __shared__ __nv_bfloat16 fsm[];
    __nv_bfloat16* Qh = fsm;                // [128][72]
    __nv_bfloat16* Ql = Qh + 128 * FP;
    __nv_bfloat16* Kh = Ql + 128 * FP;      // [64][72]
    __nv_bfloat16* Kl = Kh + 64 * FP;
    __nv_bfloat16* Vh = Kl + 64 * FP;
    __nv_bfloat16* Vl = Vh + 64 * FP;

    const int tid = threadIdx.x, lane = tid & 31, wid = tid >> 5;
    const int b = blockIdx.z, h = blockIdx.y, q0 = blockIdx.x * 128;
    const __nv_bfloat16* gq = qs + ((size_t)(b * HH + h) * SS + q0) * 128;
    const __nv_bfloat16* gk = ks + ((size_t)(b * HH + h) * SS) * 128;
    const __nv_bfloat16* gv = vs + ((size_t)(b * HH + h) * SS) * 128;

    #pragma unroll
    for (int t = 0; t < 8; t++) {
        int c = t * 256 + tid;
        int row = c >> 4, sub = c & 15;
        __nv_bfloat16* dst = (sub < 8) ? (Qh + row * FP + sub * 8)
                                       : (Ql + row * FP + (sub - 8) * 8);
        cp16(dst, gq + row * 128 + sub * 8);
    }
    CP_COMMIT();

    auto loadKV = [&](__nv_bfloat16* Ph, __nv_bfloat16* Pl,
                      const __nv_bfloat16* src, int kv0) {
        #pragma unroll
        for (int t = 0; t < 4; t++) {
            int c = t * 256 + tid;
            int row = c >> 4, sub = c & 15;
            __nv_bfloat16* dst = (sub < 8) ? (Ph + row * FP + sub * 8)
                                           : (Pl + row * FP + (sub - 8) * 8);
            cp16(dst, src + (size_t)(kv0 + row) * 128 + sub * 8);
        }
    };
    loadKV(Kh, Kl, gk, 0); CP_COMMIT();
    loadKV(Vh, Vl, gv, 0); CP_COMMIT();

    const int g = lane >> 2, t4 = lane & 3;
    float m0 = -1e30f, m1 = -1e30f, l0 = 0.f, l1 = 0.f;
    float o[8][4];
    #pragma unroll
    for (int j = 0; j < 8; j++)
        #pragma unroll
        for (int r = 0; r < 4; r++) o[j][r] = 0.f;

    const int NT = SS / 64;
    for (int t = 0; t < NT; t++) {
        CP_WAIT(1);
        __syncthreads();

        float s[8][4];
        #pragma unroll
        for (int j = 0; j < 8; j++)
            #pragma unroll
            for (int r = 0; r < 4; r++) s[j][r] = 0.f;

        #pragma unroll
        for (int k16 = 0; k16 < 64; k16 += 16) {
            uint32_t Ah[4], Al[4];
            int arow = wid * 16 + (lane & 15);
            int acol = k16 + (lane >> 4) * 8;
            ldmA4(Ah, Qh + arow * FP + acol);
            ldmA4(Al, Ql + arow * FP + acol);
            #pragma unroll
            for (int nn = 0; nn < 4; nn++) {
                int n0 = nn * 16;
                int brow = n0 + (lane & 7) + ((lane >> 4) ? 8 : 0);
                int bcol = k16 + ((lane >> 3) & 1) * 8;
                uint32_t Bh[4], Bl[4];
                ldmA4(Bh, Kh + brow * FP + bcol);
                mma16816(s[2*nn],   Ah[0], Ah[1], Ah[2], Ah[3], Bh[0], Bh[1]);
                mma16816(s[2*nn+1], Ah[0], Ah[1], Ah[2], Ah[3], Bh[2], Bh[3]);
                mma16816(s[2*nn],   Al[0], Al[1], Al[2], Al[3], Bh[0], Bh[1]);
                mma16816(s[2*nn+1], Al[0], Al[1], Al[2], Al[3], Bh[2], Bh[3]);
                ldmA4(Bl, Kl + brow * FP + bcol);
                mma16816(s[2*nn],   Ah[0], Ah[1], Ah[2], Ah[3], Bl[0], Bl[1]);
                mma16816(s[2*nn+1], Ah[0], Ah[1], Ah[2], Ah[3], Bl[2], Bl[3]);
            }
        }
        __syncthreads();
        if (t + 1 < NT) { loadKV(Kh, Kl, gk, (t + 1) * 64); CP_COMMIT(); CP_WAIT(1); }
        else           { CP_WAIT(0); }

        float mx0 = -1e30f, mx1 = -1e30f;
        #pragma unroll
        for (int j = 0; j < 8; j++) {
            mx0 = fmaxf(mx0, fmaxf(s[j][0], s[j][1]));
            mx1 = fmaxf(mx1, fmaxf(s[j][2], s[j][3]));
        }
        mx0 = fmaxf(mx0, __shfl_xor_sync(0xffffffffu, mx0, 1));
        mx0 = fmaxf(mx0, __shfl_xor_sync(0xffffffffu, mx0, 2));
        mx1 = fmaxf(mx1, __shfl_xor_sync(0xffffffffu, mx1, 1));
        mx1 = fmaxf(mx1, __shfl_xor_sync(0xffffffffu, mx1, 2));
        float mn0 = fmaxf(m0, mx0), mn1 = fmaxf(m1, mx1);
        float a0 = __expf(m0 - mn0), a1 = __expf(m1 - mn1);
        float sum0 = 0.f, sum1 = 0.f;
        #pragma unroll
        for (int j = 0; j < 8; j++) {
            s[j][0] = __expf(s[j][0] - mn0);
            s[j][1] = __expf(s[j][1] - mn0);
            s[j][2] = __expf(s[j][2] - mn1);
            s[j][3] = __expf(s[j][3] - mn1);
            sum0 += s[j][0] + s[j][1];
            sum1 += s[j][2] + s[j][3];
        }
        sum0 += __shfl_xor_sync(0xffffffffu, sum0, 1);
        sum0 += __shfl_xor_sync(0xffffffffu, sum0, 2);
        sum1 += __shfl_xor_sync(0xffffffffu, sum1, 1);
        sum1 += __shfl_xor_sync(0xffffffffu, sum1, 2);
        l0 = l0 * a0 + sum0; l1 = l1 * a1 + sum1;
        m0 = mn0; m1 = mn1;
        #pragma unroll
        for (int j = 0; j < 8; j++) {
            o[j][0] *= a0; o[j][1] *= a0;
            o[j][2] *= a1; o[j][3] *= a1;
        }

        uint32_t aPh[4][4], aPl[4][4];
        #pragma unroll
        for (int j = 0; j < 4; j++) {
            packsplit2(s[2*j][0],   s[2*j][1],   aPh[j][0], aPl[j][0]);
            packsplit2(s[2*j][2],   s[2*j][3],   aPh[j][1], aPl[j][1]);
            packsplit2(s[2*j+1][0], s[2*j+1][1], aPh[j][2], aPl[j][2]);
            packsplit2(s[2*j+1][2], s[2*j+1][3], aPh[j][3], aPl[j][3]);
        }

        __syncthreads();

        #pragma unroll
        for (int j = 0; j < 4; j++) {
            int k0 = j * 16;
            int vrow = k0 + (lane & 7) + (((lane >> 3) & 1) ? 8 : 0);
            #pragma unroll
            for (int nn = 0; nn < 4; nn++) {
                int n0 = nn * 16 + ((lane >> 4) ? 8 : 0);
                uint32_t Bv[4], Bl2[4];
                ldmT4(Bv, Vh + vrow * FP + n0);
                mma16816(o[2*nn],   aPh[j][0], aPh[j][1], aPh[j][2], aPh[j][3], Bv[0], Bv[1]);
                mma16816(o[2*nn+1], aPh[j][0], aPh[j][1], aPh[j][2], aPh[j][3], Bv[2], Bv[3]);
                mma16816(o[2*nn],   aPl[j][0], aPl[j][1], aPl[j][2], aPl[j][3], Bv[0], Bv[1]);
                mma16816(o[2*nn+1], aPl[j][0], aPl[j][1], aPl[j][2], aPl[j][3], Bv[2], Bv[3]);
                ldmT4(Bl2, Vl + vrow * FP + n0);
                mma16816(o[2*nn],   aPh[j][0], aPh[j][1], aPh[j][2], aPh[j][3], Bl2[0], Bl2[1]);
                mma16816(o[2*nn+1], aPh[j][0], aPh[j][1], aPh[j][2], aPh[j][3], Bl2[2], Bl2[3]);
            }
        }
        __syncthreads();
        if (t + 1 < NT) { loadKV(Vh, Vl, gv, (t + 1) * 64); CP_COMMIT(); }
    }

    float inv0 = 1.0f / l0, inv1 = 1.0f / l1;
    int row0 = (b * SS) + q0 + wid * 16 + g;
    int row1 = row0 + 8;
    #pragma unroll
    for (int nt = 0; nt < 8; nt++) {
        int col = h * HD + nt * 8 + t4 * 2;
        uint32_t hp, lp;
        packsplit2(o[nt][0] * inv0, o[nt][1] * inv0, hp, lp);
        uint32_t* d0 = reinterpret_cast<uint32_t*>(ctxs + (size_t)row0 * 2 * DD + col);
        d0[0] = hp; d0[DD / 2] = lp;
        packsplit2(o[nt][2] * inv1, o[nt][3] * inv1, hp, lp);
        uint32_t* d1 = reinterpret_cast<uint32_t*>(ctxs + (size_t)row1 * 2 * DD + col);
        d1[0] = hp; d1[DD / 2] = lp;
    }
}

// ---------------- driver ----------------
#define GEMM_SMEM (2 * GST * 2)                 // 147456 B
#define FLASH_SMEM ((128*FP*2 + 64*FP*4) * 2)   // 73728 B

extern "C" void kernel_launch(void* const* d_in, const int* in_sizes, int n_in,
                              void* d_out, int out_size)
{
    const float* x     = (const float*)d_in[0];
    const float* wq    = (const float*)d_in[1];
    const float* bq    = (const float*)d_in[2];
    const float* wk    = (const float*)d_in[3];
    const float* bk    = (const float*)d_in[4];
    const float* wv    = (const float*)d_in[5];
    const float* bv    = (const float*)d_in[6];
    const float* wo    = (const float*)d_in[7];
    const float* bo    = (const float*)d_in[8];
    const float* w1    = (const float*)d_in[9];
    const float* b1    = (const float*)d_in[10];
    const float* w2    = (const float*)d_in[11];
    const float* b2    = (const float*)d_in[12];
    const float* ln1_g = (const float*)d_in[13];
    const float* ln1_b = (const float*)d_in[14];
    const float* ln2_g = (const float*)d_in[15];
    const float* ln2_b = (const float*)d_in[16];
    const float* lscal = (const float*)d_in[17];
    float* out = (float*)d_out;

    __nv_bfloat16 *xns, *ctxs, *h1s, *wqkvs, *wos, *w1s, *w2s, *qsb, *ksb, *vsb;
    float *qkvf, *x2f, *bqkv;
    cudaGetSymbolAddress((void**)&xns,   g_xns);
    cudaGetSymbolAddress((void**)&ctxs,  g_ctxs);
    cudaGetSymbolAddress((void**)&h1s,   g_h1s);
    cudaGetSymbolAddress((void**)&wqkvs, g_wqkvs);
    cudaGetSymbolAddress((void**)&wos,   g_wos);
    cudaGetSymbolAddress((void**)&w1s,   g_w1s);
    cudaGetSymbolAddress((void**)&w2s,   g_w2s);
    cudaGetSymbolAddress((void**)&qkvf,  g_qkv);
    cudaGetSymbolAddress((void**)&x2f,   g_x2);
    cudaGetSymbolAddress((void**)&qsb,   g_qsb);
    cudaGetSymbolAddress((void**)&ksb,   g_ksb);
    cudaGetSymbolAddress((void**)&vsb,   g_vsb);
    cudaGetSymbolAddress((void**)&bqkv,  g_bqkv);

    cudaFuncSetAttribute(hmma_gemm_kernel<0>, cudaFuncAttributeMaxDynamicSharedMemorySize, GEMM_SMEM);
    cudaFuncSetAttribute(hmma_gemm_kernel<1>, cudaFuncAttributeMaxDynamicSharedMemorySize, GEMM_SMEM);
    cudaFuncSetAttribute(hmma_gemm_kernel<2>, cudaFuncAttributeMaxDynamicSharedMemorySize, GEMM_SMEM);
    cudaFuncSetAttribute(flash_tc_kernel, cudaFuncAttributeMaxDynamicSharedMemorySize, FLASH_SMEM);

    dim3 wb(32, 8);
    // launches 1-3; ncu captures launch #4 = QKV GEMM
    wsplit3_kernel<<<dim3(DD/32, DD/32, 3), wb>>>(wq, wk, wv, wqkvs);
    packb_kernel<<<12, 256>>>(bq, bk, bv, bqkv);
    ln_split_kernel<<<MM, 256>>>(x, ln1_g, ln1_b, xns);

    dim3 gQKV(3 * DD / 128, MM / 128);   // (24, 32)
    dim3 gD  (DD / 128, MM / 128);       // (8, 32)
    dim3 gMLP1(MLPD / 128, MM / 128);    // (32, 32)

    // launch #4: the hot QKV GEMM (profiled)
    hmma_gemm_kernel<0><<<gQKV, 512, GEMM_SMEM>>>(xns, wqkvs, bqkv, nullptr, qkvf, nullptr, 3 * DD, DD);

    // remaining weight splits (stream-ordered; complete before their GEMMs)
    wsplit_kernel<<<dim3(DD/32,  DD/32),  wb>>>(wo, wos, DD,   DD);
    wsplit_kernel<<<dim3(MLPD/32, DD/32), wb>>>(w1, w1s, DD,   MLPD);
    wsplit_kernel<<<dim3(DD/32, MLPD/32), wb>>>(w2, w2s, MLPD, DD);

    qkvprep_kernel<<<(MM * HH * 32) / 256, 256>>>(qkvf, lscal, qsb, ksb, vsb);

    flash_tc_kernel<<<dim3(SS / 128, HH, BB), 256, FLASH_SMEM>>>(qsb, ksb, vsb, ctxs);

    hmma_gemm_kernel<1><<<gD, 512, GEMM_SMEM>>>(ctxs, wos, bo, x, x2f, nullptr, DD, DD);

    ln_split_kernel<<<MM, 256>>>(x2f, ln2_g, ln2_b, xns);

    hmma_gemm_kernel<2><<<gMLP1, 512, GEMM_SMEM>>>(xns, w1s, b1, nullptr, nullptr, h1s, MLPD, DD);

    hmma_gemm_kernel<1><<<gD, 512, GEMM_SMEM>>>(h1s, w2s, b2, x2f, out, nullptr, DD, MLPD);
}